// round 3
// baseline (speedup 1.0000x reference)
#include <cuda_runtime.h>
#include <cuda_bf16.h>

#define N_NODES 50000
#define N_EDGES 800000
#define HEADS 8
#define HID 16
#define NCLS 10

// ---------------- scratch (device globals; no allocation) ----------------
__device__ __align__(128) float g_feat[N_NODES * 128];   // transformed features
__device__ __align__(128) float g_hbuf[N_NODES * 128];   // layer output / next input
__device__ __align__(128) float g_el[N_NODES * HEADS];
__device__ __align__(128) float g_er[N_NODES * HEADS];
__device__ __align__(128) float g_feat5[N_NODES * NCLS];
__device__ __align__(128) float g_el5[N_NODES];
__device__ __align__(128) float g_er5[N_NODES];
__device__ __align__(128) int   g_rowptr[N_NODES + 1];
__device__ __align__(128) int   g_wptr[N_NODES];
__device__ __align__(128) int   g_eidx[N_EDGES];

#define NEG_INF (-3.0e38f)

// ---------------- CSR build ----------------
__global__ void k_zero_rowptr() {
    int i = blockIdx.x * blockDim.x + threadIdx.x;
    if (i <= N_NODES) g_rowptr[i] = 0;
}

__global__ void k_hist(const int* __restrict__ dst) {
    int i = blockIdx.x * blockDim.x + threadIdx.x;
    if (i < N_EDGES) atomicAdd(&g_rowptr[dst[i] + 1], 1);
}

__global__ void k_scan() {
    __shared__ int sums[1024];
    const int TOT = N_NODES + 1;
    const int CH = (TOT + 1023) / 1024;
    int t = threadIdx.x;
    int beg = t * CH;
    int fin = beg + CH; if (fin > TOT) fin = TOT;
    int s = 0;
    for (int i = beg; i < fin; i++) s += g_rowptr[i];
    sums[t] = s;
    __syncthreads();
    for (int off = 1; off < 1024; off <<= 1) {
        int v = 0;
        if (t >= off) v = sums[t - off];
        __syncthreads();
        sums[t] += v;
        __syncthreads();
    }
    int run = (t > 0) ? sums[t - 1] : 0;
    for (int i = beg; i < fin; i++) { run += g_rowptr[i]; g_rowptr[i] = run; }
}

__global__ void k_wptr() {
    int i = blockIdx.x * blockDim.x + threadIdx.x;
    if (i < N_NODES) g_wptr[i] = g_rowptr[i];
}

__global__ void k_scatter(const int* __restrict__ dst) {
    int i = blockIdx.x * blockDim.x + threadIdx.x;
    if (i < N_EDGES) {
        int pos = atomicAdd(&g_wptr[dst[i]], 1);
        g_eidx[pos] = i;
    }
}

// ---------------- GEMM 128x128 (fused feat = in @ W) ----------------
// Block 256 threads, 64 rows/block. W(64KB)+h-tile(32KB) in dynamic smem.
// Thread: 4 rows x 8 cols (cols strided by 16 -> conflict-free smem reads).
__global__ void __launch_bounds__(256) gemm128_kernel(const float* __restrict__ in,
                                                      const float* __restrict__ W) {
    extern __shared__ float sm[];
    float* Wsm = sm;            // 128*128
    float* hs  = sm + 16384;    // 64*128
    int tid = threadIdx.x;
    int row0 = blockIdx.x * 64;

    for (int i = tid; i < 4096; i += 256)
        ((float4*)Wsm)[i] = ((const float4*)W)[i];
    for (int q = tid; q < 64 * 32; q += 256) {
        int r = q >> 5, c4 = q & 31;
        int gr = row0 + r;
        float4 v = make_float4(0.f, 0.f, 0.f, 0.f);
        if (gr < N_NODES) v = ((const float4*)in)[gr * 32 + c4];
        ((float4*)hs)[q] = v;
    }
    __syncthreads();

    int cg = tid & 15;        // col within head (d)
    int rslot = tid >> 4;     // 0..15 -> 4 rows each
    float acc[4][8];
#pragma unroll
    for (int i = 0; i < 4; i++)
#pragma unroll
        for (int j = 0; j < 8; j++) acc[i][j] = 0.f;

    for (int k4 = 0; k4 < 128; k4 += 4) {
        float4 hv[4];
#pragma unroll
        for (int i = 0; i < 4; i++)
            hv[i] = *(const float4*)&hs[(rslot * 4 + i) * 128 + k4];
#pragma unroll
        for (int kk = 0; kk < 4; kk++) {
            float w[8];
#pragma unroll
            for (int j = 0; j < 8; j++) w[j] = Wsm[(k4 + kk) * 128 + cg + 16 * j];
#pragma unroll
            for (int i = 0; i < 4; i++) {
                float hvv = (kk == 0) ? hv[i].x : (kk == 1) ? hv[i].y : (kk == 2) ? hv[i].z : hv[i].w;
#pragma unroll
                for (int j = 0; j < 8; j++) acc[i][j] = fmaf(hvv, w[j], acc[i][j]);
            }
        }
    }
#pragma unroll
    for (int i = 0; i < 4; i++) {
        int r = row0 + rslot * 4 + i;
        if (r < N_NODES) {
#pragma unroll
            for (int j = 0; j < 8; j++)
                g_feat[r * 128 + cg + 16 * j] = acc[i][j];
        }
    }
}

// ---------------- el/er per (node, head) ----------------
__global__ void elr_kernel(const float* __restrict__ al, const float* __restrict__ ar) {
    __shared__ float sal[128], sar[128];
    int tid = threadIdx.x;
    if (tid < 128) { sal[tid] = al[tid]; sar[tid] = ar[tid]; }
    __syncthreads();
    int idx = blockIdx.x * blockDim.x + tid;
    if (idx >= N_NODES * HEADS) return;
    int hb = (idx & 7) * 16;
    int base = idx * 16;   // == n*128 + h*16
    float se = 0.f, sr = 0.f;
#pragma unroll
    for (int q = 0; q < 16; q += 4) {
        float4 f = *(const float4*)&g_feat[base + q];
        se += f.x * sal[hb + q] + f.y * sal[hb + q + 1] + f.z * sal[hb + q + 2] + f.w * sal[hb + q + 3];
        sr += f.x * sar[hb + q] + f.y * sar[hb + q + 1] + f.z * sar[hb + q + 2] + f.w * sar[hb + q + 3];
    }
    g_el[idx] = se;
    g_er[idx] = sr;
}

// ---------------- per-dst softmax aggregation (8 heads, 128 dims) ----------------
// One warp per destination node. Lane owns 4 output dims (head = lane/4... lane*4/16).
__global__ void __launch_bounds__(256) aggregate_kernel(const int* __restrict__ src, int activate) {
    int warp = (blockIdx.x * blockDim.x + threadIdx.x) >> 5;
    int lane = threadIdx.x & 31;
    if (warp >= N_NODES) return;
    int n = warp;
    int start = g_rowptr[n], end = g_rowptr[n + 1];
    if (start == end) {
        float4 z = make_float4(0.f, 0.f, 0.f, 0.f);
        *(float4*)&g_hbuf[n * 128 + lane * 4] = z;
        return;
    }
    int h8 = lane & 7;
    float erv = g_er[n * HEADS + h8];

    // pass 1: per-head max (4 edges x 8 heads per iteration)
    float mx = NEG_INF;
    for (int base = start; base < end; base += 4) {
        int j = base + (lane >> 3);
        float v = NEG_INF;
        if (j < end) {
            int s = src[g_eidx[j]];
            float e = g_el[s * HEADS + h8] + erv;
            v = (e >= 0.f) ? e : 0.2f * e;
        }
        v = fmaxf(v, __shfl_xor_sync(0xffffffffu, v, 8));
        v = fmaxf(v, __shfl_xor_sync(0xffffffffu, v, 16));
        mx = fmaxf(mx, v);
    }

    // pass 2: exp, denom, weighted accumulate of feat[src]
    float dn = 0.f;
    float4 acc = make_float4(0.f, 0.f, 0.f, 0.f);
    int hq = lane >> 2;  // source lane holding my head's ex/denom
    for (int j = start; j < end; j++) {
        int s = src[g_eidx[j]];
        float e = g_el[s * HEADS + h8] + erv;
        e = (e >= 0.f) ? e : 0.2f * e;
        float ex = expf(e - mx);
        dn += ex;
        float exb = __shfl_sync(0xffffffffu, ex, hq);
        float4 f = *(const float4*)&g_feat[s * 128 + lane * 4];
        acc.x = fmaf(exb, f.x, acc.x);
        acc.y = fmaf(exb, f.y, acc.y);
        acc.z = fmaf(exb, f.z, acc.z);
        acc.w = fmaf(exb, f.w, acc.w);
    }
    float dnb = __shfl_sync(0xffffffffu, dn, hq);
    float inv = 1.0f / dnb;
    float4 r;
    r.x = acc.x * inv; r.y = acc.y * inv; r.z = acc.z * inv; r.w = acc.w * inv;
    if (activate) {
        r.x = (r.x > 0.f) ? r.x : expm1f(r.x);
        r.y = (r.y > 0.f) ? r.y : expm1f(r.y);
        r.z = (r.z > 0.f) ? r.z : expm1f(r.z);
        r.w = (r.w > 0.f) ? r.w : expm1f(r.w);
    }
    *(float4*)&g_hbuf[n * 128 + lane * 4] = r;
}

// ---------------- layer 4: 128 -> 10 GEMM ----------------
__global__ void __launch_bounds__(320) gemm5_kernel(const float* __restrict__ W4) {
    __shared__ float Ws[1280];
    __shared__ float hs[32 * 128];
    int tid = threadIdx.x;
    int n0 = blockIdx.x * 32;
    for (int i = tid; i < 1280; i += 320) Ws[i] = W4[i];
    for (int i = tid; i < 4096; i += 320) {
        int gr = n0 + (i >> 7);
        hs[i] = (gr < N_NODES) ? g_hbuf[gr * 128 + (i & 127)] : 0.f;
    }
    __syncthreads();
    int nl = tid / 10, c = tid - nl * 10;
    if (nl >= 32) return;
    int n = n0 + nl;
    if (n >= N_NODES) return;
    float a = 0.f;
#pragma unroll 8
    for (int k = 0; k < 128; k++) a = fmaf(hs[nl * 128 + k], Ws[k * 10 + c], a);
    g_feat5[n * 10 + c] = a;
}

__global__ void elr5_kernel(const float* __restrict__ al4, const float* __restrict__ ar4) {
    int n = blockIdx.x * blockDim.x + threadIdx.x;
    if (n >= N_NODES) return;
    float se = 0.f, sr = 0.f;
#pragma unroll
    for (int c = 0; c < 10; c++) {
        float f = g_feat5[n * 10 + c];
        se += f * al4[c];
        sr += f * ar4[c];
    }
    g_el5[n] = se;
    g_er5[n] = sr;
}

// ---------------- layer 4 aggregation (1 head, 10 dims) -> d_out ----------------
__global__ void __launch_bounds__(256) agg5_kernel(const int* __restrict__ src, float* __restrict__ out) {
    int warp = (blockIdx.x * blockDim.x + threadIdx.x) >> 5;
    int lane = threadIdx.x & 31;
    if (warp >= N_NODES) return;
    int n = warp;
    int start = g_rowptr[n], end = g_rowptr[n + 1];
    if (start == end) {
        if (lane < 10) out[n * 10 + lane] = 0.f;
        return;
    }
    float ern = g_er5[n];
    float mx = NEG_INF;
    for (int base = start; base < end; base += 32) {
        int j = base + lane;
        float v = NEG_INF;
        if (j < end) {
            int s = src[g_eidx[j]];
            float e = g_el5[s] + ern;
            v = (e >= 0.f) ? e : 0.2f * e;
        }
        mx = fmaxf(mx, v);
    }
#pragma unroll
    for (int off = 16; off >= 1; off >>= 1) mx = fmaxf(mx, __shfl_xor_sync(0xffffffffu, mx, off));

    float dn = 0.f;
    float acc[10];
#pragma unroll
    for (int c = 0; c < 10; c++) acc[c] = 0.f;
    for (int base = start; base < end; base += 32) {
        int j = base + lane;
        if (j < end) {
            int s = src[g_eidx[j]];
            float e = g_el5[s] + ern;
            e = (e >= 0.f) ? e : 0.2f * e;
            float ex = expf(e - mx);
            dn += ex;
#pragma unroll
            for (int c = 0; c < 10; c++) acc[c] = fmaf(ex, g_feat5[s * 10 + c], acc[c]);
        }
    }
#pragma unroll
    for (int off = 16; off >= 1; off >>= 1) dn += __shfl_xor_sync(0xffffffffu, dn, off);
    float res = 0.f;
#pragma unroll
    for (int c = 0; c < 10; c++) {
        float t = acc[c];
#pragma unroll
        for (int off = 16; off >= 1; off >>= 1) t += __shfl_xor_sync(0xffffffffu, t, off);
        if (lane == c) res = t;
    }
    if (lane < 10) out[n * 10 + lane] = res / dn;
}

// ---------------- launch ----------------
extern "C" void kernel_launch(void* const* d_in, const int* in_sizes, int n_in,
                              void* d_out, int out_size) {
    const float* h   = (const float*)d_in[0];
    const int*   src = (const int*)d_in[1];
    const int*   dst = (const int*)d_in[2];
    const float* W[5]  = {(const float*)d_in[3],  (const float*)d_in[6],  (const float*)d_in[9],
                          (const float*)d_in[12], (const float*)d_in[15]};
    const float* al[5] = {(const float*)d_in[4],  (const float*)d_in[7],  (const float*)d_in[10],
                          (const float*)d_in[13], (const float*)d_in[16]};
    const float* ar[5] = {(const float*)d_in[5],  (const float*)d_in[8],  (const float*)d_in[11],
                          (const float*)d_in[14], (const float*)d_in[17]};
    float* out = (float*)d_out;

    cudaFuncSetAttribute(gemm128_kernel, cudaFuncAttributeMaxDynamicSharedMemorySize, 98304);

    void* hbuf_p = nullptr;
    cudaGetSymbolAddress(&hbuf_p, g_hbuf);
    const float* hbuf = (const float*)hbuf_p;

    // CSR build (per launch; deterministic modulo within-segment order)
    k_zero_rowptr<<<(N_NODES + 1 + 255) / 256, 256>>>();
    k_hist<<<(N_EDGES + 255) / 256, 256>>>(dst);
    k_scan<<<1, 1024>>>();
    k_wptr<<<(N_NODES + 255) / 256, 256>>>();
    k_scatter<<<(N_EDGES + 255) / 256, 256>>>(dst);

    const float* cur = h;
    for (int l = 0; l < 4; l++) {
        gemm128_kernel<<<(N_NODES + 63) / 64, 256, 98304>>>(cur, W[l]);
        elr_kernel<<<(N_NODES * HEADS + 255) / 256, 256>>>(al[l], ar[l]);
        aggregate_kernel<<<(N_NODES * 32 + 255) / 256, 256>>>(src, 1);
        cur = hbuf;
    }
    gemm5_kernel<<<(N_NODES + 31) / 32, 320>>>(W[4]);
    elr5_kernel<<<(N_NODES + 255) / 256, 256>>>(al[4], ar[4]);
    agg5_kernel<<<(N_NODES * 32 + 255) / 256, 256>>>(src, out);
}

// round 5
// speedup vs baseline: 1.1296x; 1.1296x over previous
#include <cuda_runtime.h>
#include <cuda_bf16.h>

#define N_NODES 50000
#define N_EDGES 800000
#define HEADS 8
#define HID 16
#define NCLS 10

// ---------------- scratch (device globals; no allocation) ----------------
__device__ __align__(128) float g_feat[N_NODES * 128];   // transformed features
__device__ __align__(128) float g_hbuf[N_NODES * 128];   // layer output / next input
__device__ __align__(128) float g_el[N_NODES * HEADS];
__device__ __align__(128) float g_er[N_NODES * HEADS];
__device__ __align__(128) float g_wa[4 * 128 * 16];      // folded attention weights per layer
__device__ __align__(128) float g_feat5[N_NODES * NCLS];
__device__ __align__(128) float g_el5[N_NODES];
__device__ __align__(128) float g_er5[N_NODES];
__device__ __align__(128) int   g_rowptr[N_NODES + 1];
__device__ __align__(128) int   g_wptr[N_NODES];
__device__ __align__(128) int   g_srcs[N_EDGES];         // src node id, CSR-sorted by dst

#define NEG_INF (-3.0e38f)

// ---------------- CSR build ----------------
__global__ void k_zero_rowptr() {
    int i = blockIdx.x * blockDim.x + threadIdx.x;
    if (i <= N_NODES) g_rowptr[i] = 0;
}

__global__ void k_hist(const int* __restrict__ dst) {
    int i = blockIdx.x * blockDim.x + threadIdx.x;
    if (i < N_EDGES) atomicAdd(&g_rowptr[dst[i] + 1], 1);
}

// single-block scan; also writes wptr (= rowptr start of each node)
__global__ void k_scan() {
    __shared__ int sums[1024];
    const int TOT = N_NODES + 1;
    const int CH = (TOT + 1023) / 1024;
    int t = threadIdx.x;
    int beg = t * CH;
    int fin = beg + CH; if (fin > TOT) fin = TOT;
    int s = 0;
    for (int i = beg; i < fin; i++) s += g_rowptr[i];
    sums[t] = s;
    __syncthreads();
    for (int off = 1; off < 1024; off <<= 1) {
        int v = 0;
        if (t >= off) v = sums[t - off];
        __syncthreads();
        sums[t] += v;
        __syncthreads();
    }
    int run = (t > 0) ? sums[t - 1] : 0;
    for (int i = beg; i < fin; i++) {
        run += g_rowptr[i];
        g_rowptr[i] = run;
        if (i < N_NODES) g_wptr[i] = run;
    }
}

__global__ void k_scatter(const int* __restrict__ src, const int* __restrict__ dst) {
    int i = blockIdx.x * blockDim.x + threadIdx.x;
    if (i < N_EDGES) {
        int pos = atomicAdd(&g_wptr[dst[i]], 1);
        g_srcs[pos] = src[i];
    }
}

// ---------------- fold al/ar into W: wa[k][c] (c<8: el head c, c>=8: er head c-8) ----------------
__global__ void k_wa(const float* __restrict__ W0, const float* __restrict__ a0l, const float* __restrict__ a0r,
                     const float* __restrict__ W1, const float* __restrict__ a1l, const float* __restrict__ a1r,
                     const float* __restrict__ W2, const float* __restrict__ a2l, const float* __restrict__ a2r,
                     const float* __restrict__ W3, const float* __restrict__ a3l, const float* __restrict__ a3r) {
    int idx = blockIdx.x * blockDim.x + threadIdx.x;
    if (idx >= 4 * 128 * 16) return;
    int l = idx >> 11;
    int k = (idx >> 4) & 127;
    int c = idx & 15;
    int h = c & 7;
    const float* W = (l == 0) ? W0 : (l == 1) ? W1 : (l == 2) ? W2 : W3;
    const float* a;
    if (c < 8) a = (l == 0) ? a0l : (l == 1) ? a1l : (l == 2) ? a2l : a3l;
    else       a = (l == 0) ? a0r : (l == 1) ? a1r : (l == 2) ? a2r : a3r;
    float s = 0.f;
#pragma unroll
    for (int d = 0; d < 16; d++) s += W[k * 128 + h * 16 + d] * a[h * 16 + d];
    g_wa[l * 2048 + k * 16 + c] = s;
}

// ---------------- GEMM 128x(128+16): feat = in @ W, el/er = in @ wa ----------------
__global__ void __launch_bounds__(256) gemm128_kernel(const float* __restrict__ in,
                                                      const float* __restrict__ W,
                                                      const float* __restrict__ wa) {
    extern __shared__ float sm[];
    float* Wsm = sm;            // 128*128 = 16384 floats
    float* hs  = sm + 16384;    // 64*128  =  8192 floats
    float* was = sm + 24576;    // 128*16  =  2048 floats
    int tid = threadIdx.x;
    int row0 = blockIdx.x * 64;

    for (int i = tid; i < 4096; i += 256)
        ((float4*)Wsm)[i] = ((const float4*)W)[i];
    for (int i = tid; i < 512; i += 256)
        ((float4*)was)[i] = ((const float4*)wa)[i];
    for (int q = tid; q < 64 * 32; q += 256) {
        int r = q >> 5, c4 = q & 31;
        int gr = row0 + r;
        float4 v = make_float4(0.f, 0.f, 0.f, 0.f);
        if (gr < N_NODES) v = ((const float4*)in)[gr * 32 + c4];
        ((float4*)hs)[q] = v;
    }
    __syncthreads();

    int cg = tid & 15;        // col within head (d); also the extra-col index
    int rslot = tid >> 4;     // 0..15 -> 4 rows each
    float acc[4][8];
    float acc2[4];
#pragma unroll
    for (int i = 0; i < 4; i++) {
        acc2[i] = 0.f;
#pragma unroll
        for (int j = 0; j < 8; j++) acc[i][j] = 0.f;
    }

    for (int k4 = 0; k4 < 128; k4 += 4) {
        float4 hv[4];
#pragma unroll
        for (int i = 0; i < 4; i++)
            hv[i] = *(const float4*)&hs[(rslot * 4 + i) * 128 + k4];
#pragma unroll
        for (int kk = 0; kk < 4; kk++) {
            float w[8];
#pragma unroll
            for (int j = 0; j < 8; j++) w[j] = Wsm[(k4 + kk) * 128 + cg + 16 * j];
            float wav = was[(k4 + kk) * 16 + cg];
#pragma unroll
            for (int i = 0; i < 4; i++) {
                float hvv = (kk == 0) ? hv[i].x : (kk == 1) ? hv[i].y : (kk == 2) ? hv[i].z : hv[i].w;
#pragma unroll
                for (int j = 0; j < 8; j++) acc[i][j] = fmaf(hvv, w[j], acc[i][j]);
                acc2[i] = fmaf(hvv, wav, acc2[i]);
            }
        }
    }
#pragma unroll
    for (int i = 0; i < 4; i++) {
        int r = row0 + rslot * 4 + i;
        if (r < N_NODES) {
#pragma unroll
            for (int j = 0; j < 8; j++)
                g_feat[r * 128 + cg + 16 * j] = acc[i][j];
            if (cg < 8) g_el[r * 8 + cg] = acc2[i];
            else        g_er[r * 8 + cg - 8] = acc2[i];
        }
    }
}

// ---------------- per-dst softmax aggregation (8 heads, 128 dims) ----------------
// One warp per destination node. Lane owns 4 output dims.
__global__ void __launch_bounds__(256) aggregate_kernel(int activate) {
    int warp = (blockIdx.x * blockDim.x + threadIdx.x) >> 5;
    int lane = threadIdx.x & 31;
    if (warp >= N_NODES) return;
    int n = warp;
    int start = g_rowptr[n], end = g_rowptr[n + 1];
    if (start == end) {
        float4 z = make_float4(0.f, 0.f, 0.f, 0.f);
        *(float4*)&g_hbuf[n * 128 + lane * 4] = z;
        return;
    }
    int h8 = lane & 7;
    float erv = g_er[n * HEADS + h8];

    // pass 1: per-head max (4 edges x 8 heads per iteration)
    float mx = NEG_INF;
    for (int base = start; base < end; base += 4) {
        int j = base + (lane >> 3);
        float v = NEG_INF;
        if (j < end) {
            int s = g_srcs[j];
            float e = g_el[s * HEADS + h8] + erv;
            v = (e >= 0.f) ? e : 0.2f * e;
        }
        v = fmaxf(v, __shfl_xor_sync(0xffffffffu, v, 8));
        v = fmaxf(v, __shfl_xor_sync(0xffffffffu, v, 16));
        mx = fmaxf(mx, v);
    }

    // pass 2: exp, denom, weighted accumulate of feat[src]; 2x unrolled for MLP
    float dn = 0.f;
    float4 acc = make_float4(0.f, 0.f, 0.f, 0.f);
    int hq = lane >> 2;  // source lane holding my head's ex
    int j = start;
    for (; j + 1 < end; j += 2) {
        int s0 = g_srcs[j];
        int s1 = g_srcs[j + 1];
        float e0 = g_el[s0 * HEADS + h8] + erv;
        float e1 = g_el[s1 * HEADS + h8] + erv;
        e0 = (e0 >= 0.f) ? e0 : 0.2f * e0;
        e1 = (e1 >= 0.f) ? e1 : 0.2f * e1;
        float ex0 = __expf(e0 - mx);
        float ex1 = __expf(e1 - mx);
        dn += ex0 + ex1;
        float b0 = __shfl_sync(0xffffffffu, ex0, hq);
        float b1 = __shfl_sync(0xffffffffu, ex1, hq);
        float4 f0 = *(const float4*)&g_feat[s0 * 128 + lane * 4];
        float4 f1 = *(const float4*)&g_feat[s1 * 128 + lane * 4];
        acc.x = fmaf(b0, f0.x, acc.x);
        acc.y = fmaf(b0, f0.y, acc.y);
        acc.z = fmaf(b0, f0.z, acc.z);
        acc.w = fmaf(b0, f0.w, acc.w);
        acc.x = fmaf(b1, f1.x, acc.x);
        acc.y = fmaf(b1, f1.y, acc.y);
        acc.z = fmaf(b1, f1.z, acc.z);
        acc.w = fmaf(b1, f1.w, acc.w);
    }
    if (j < end) {
        int s0 = g_srcs[j];
        float e0 = g_el[s0 * HEADS + h8] + erv;
        e0 = (e0 >= 0.f) ? e0 : 0.2f * e0;
        float ex0 = __expf(e0 - mx);
        dn += ex0;
        float b0 = __shfl_sync(0xffffffffu, ex0, hq);
        float4 f0 = *(const float4*)&g_feat[s0 * 128 + lane * 4];
        acc.x = fmaf(b0, f0.x, acc.x);
        acc.y = fmaf(b0, f0.y, acc.y);
        acc.z = fmaf(b0, f0.z, acc.z);
        acc.w = fmaf(b0, f0.w, acc.w);
    }
    float dnb = __shfl_sync(0xffffffffu, dn, hq);
    float inv = 1.0f / dnb;
    float4 r;
    r.x = acc.x * inv; r.y = acc.y * inv; r.z = acc.z * inv; r.w = acc.w * inv;
    if (activate) {
        r.x = (r.x > 0.f) ? r.x : expm1f(r.x);
        r.y = (r.y > 0.f) ? r.y : expm1f(r.y);
        r.z = (r.z > 0.f) ? r.z : expm1f(r.z);
        r.w = (r.w > 0.f) ? r.w : expm1f(r.w);
    }
    *(float4*)&g_hbuf[n * 128 + lane * 4] = r;
}

// ---------------- layer 4: 128 -> 10 GEMM ----------------
__global__ void __launch_bounds__(320) gemm5_kernel(const float* __restrict__ W4) {
    __shared__ float Ws[1280];
    __shared__ float hs[32 * 128];
    int tid = threadIdx.x;
    int n0 = blockIdx.x * 32;
    for (int i = tid; i < 1280; i += 320) Ws[i] = W4[i];
    for (int i = tid; i < 4096; i += 320) {
        int gr = n0 + (i >> 7);
        hs[i] = (gr < N_NODES) ? g_hbuf[gr * 128 + (i & 127)] : 0.f;
    }
    __syncthreads();
    int nl = tid / 10, c = tid - nl * 10;
    if (nl >= 32) return;
    int n = n0 + nl;
    if (n >= N_NODES) return;
    float a = 0.f;
#pragma unroll 8
    for (int k = 0; k < 128; k++) a = fmaf(hs[nl * 128 + k], Ws[k * 10 + c], a);
    g_feat5[n * 10 + c] = a;
}

__global__ void elr5_kernel(const float* __restrict__ al4, const float* __restrict__ ar4) {
    int n = blockIdx.x * blockDim.x + threadIdx.x;
    if (n >= N_NODES) return;
    float se = 0.f, sr = 0.f;
#pragma unroll
    for (int c = 0; c < 10; c++) {
        float f = g_feat5[n * 10 + c];
        se += f * al4[c];
        sr += f * ar4[c];
    }
    g_el5[n] = se;
    g_er5[n] = sr;
}

// ---------------- layer 4 aggregation (1 head, 10 dims) -> d_out ----------------
__global__ void __launch_bounds__(256) agg5_kernel(float* __restrict__ out) {
    int warp = (blockIdx.x * blockDim.x + threadIdx.x) >> 5;
    int lane = threadIdx.x & 31;
    if (warp >= N_NODES) return;
    int n = warp;
    int start = g_rowptr[n], end = g_rowptr[n + 1];
    if (start == end) {
        if (lane < 10) out[n * 10 + lane] = 0.f;
        return;
    }
    float ern = g_er5[n];
    float mx = NEG_INF;
    for (int base = start; base < end; base += 32) {
        int j = base + lane;
        float v = NEG_INF;
        if (j < end) {
            int s = g_srcs[j];
            float e = g_el5[s] + ern;
            v = (e >= 0.f) ? e : 0.2f * e;
        }
        mx = fmaxf(mx, v);
    }
#pragma unroll
    for (int off = 16; off >= 1; off >>= 1) mx = fmaxf(mx, __shfl_xor_sync(0xffffffffu, mx, off));

    float dn = 0.f;
    float acc[10];
#pragma unroll
    for (int c = 0; c < 10; c++) acc[c] = 0.f;
    for (int base = start; base < end; base += 32) {
        int j = base + lane;
        if (j < end) {
            int s = g_srcs[j];
            float e = g_el5[s] + ern;
            e = (e >= 0.f) ? e : 0.2f * e;
            float ex = __expf(e - mx);
            dn += ex;
#pragma unroll
            for (int c = 0; c < 10; c++) acc[c] = fmaf(ex, g_feat5[s * 10 + c], acc[c]);
        }
    }
#pragma unroll
    for (int off = 16; off >= 1; off >>= 1) dn += __shfl_xor_sync(0xffffffffu, dn, off);
    float res = 0.f;
#pragma unroll
    for (int c = 0; c < 10; c++) {
        float t = acc[c];
#pragma unroll
        for (int off = 16; off >= 1; off >>= 1) t += __shfl_xor_sync(0xffffffffu, t, off);
        if (lane == c) res = t;
    }
    if (lane < 10) out[n * 10 + lane] = res / dn;
}

// ---------------- launch ----------------
extern "C" void kernel_launch(void* const* d_in, const int* in_sizes, int n_in,
                              void* d_out, int out_size) {
    const float* h   = (const float*)d_in[0];
    const int*   src = (const int*)d_in[1];
    const int*   dst = (const int*)d_in[2];
    const float* W[5]  = {(const float*)d_in[3],  (const float*)d_in[6],  (const float*)d_in[9],
                          (const float*)d_in[12], (const float*)d_in[15]};
    const float* al[5] = {(const float*)d_in[4],  (const float*)d_in[7],  (const float*)d_in[10],
                          (const float*)d_in[13], (const float*)d_in[16]};
    const float* ar[5] = {(const float*)d_in[5],  (const float*)d_in[8],  (const float*)d_in[11],
                          (const float*)d_in[14], (const float*)d_in[17]};
    float* out = (float*)d_out;

    cudaFuncSetAttribute(gemm128_kernel, cudaFuncAttributeMaxDynamicSharedMemorySize, 106496);

    void* hbuf_p = nullptr;
    cudaGetSymbolAddress(&hbuf_p, g_hbuf);
    const float* hbuf = (const float*)hbuf_p;
    void* wa_p = nullptr;
    cudaGetSymbolAddress(&wa_p, g_wa);
    const float* wa = (const float*)wa_p;

    // CSR build
    k_zero_rowptr<<<(N_NODES + 1 + 255) / 256, 256>>>();
    k_hist<<<(N_EDGES + 255) / 256, 256>>>(dst);
    k_scan<<<1, 1024>>>();
    k_scatter<<<(N_EDGES + 255) / 256, 256>>>(src, dst);

    // folded attention weights for layers 0..3
    k_wa<<<32, 256>>>(W[0], al[0], ar[0], W[1], al[1], ar[1],
                      W[2], al[2], ar[2], W[3], al[3], ar[3]);

    const float* cur = h;
    for (int l = 0; l < 4; l++) {
        gemm128_kernel<<<(N_NODES + 63) / 64, 256, 106496>>>(cur, W[l], wa + l * 2048);
        aggregate_kernel<<<(N_NODES * 32 + 255) / 256, 256>>>(1);
        cur = hbuf;
    }
    gemm5_kernel<<<(N_NODES + 31) / 32, 320>>>(W[4]);
    elr5_kernel<<<(N_NODES + 255) / 256, 256>>>(al[4], ar[4]);
    agg5_kernel<<<(N_NODES * 32 + 255) / 256, 256>>>(out);
}

// round 7
// speedup vs baseline: 1.3245x; 1.1725x over previous
#include <cuda_runtime.h>
#include <cuda_bf16.h>

#define N_NODES 50000
#define N_EDGES 800000
#define HEADS 8
#define HID 16
#define NCLS 10

// ---------------- scratch (device globals; no allocation) ----------------
__device__ __align__(128) float g_feat[N_NODES * 128];   // transformed features
__device__ __align__(128) float g_hbuf[N_NODES * 128];   // layer output / next input
__device__ __align__(128) float g_el[N_NODES * HEADS];
__device__ __align__(128) float g_er[N_NODES * HEADS];
__device__ __align__(128) float g_wa[4 * 128 * 16];      // folded attention weights per layer
__device__ __align__(128) float g_w4ext[128 * 12];       // W4 (10 cols) + folded al4/ar4 cols
__device__ __align__(128) float g_feat5[N_NODES * NCLS];
__device__ __align__(128) float g_el5[N_NODES];
__device__ __align__(128) float g_er5[N_NODES];
__device__ __align__(128) int   g_rowptr[N_NODES + 1];
__device__ __align__(128) int   g_wptr[N_NODES];
__device__ __align__(128) int   g_srcs[N_EDGES];         // src node id, CSR-sorted by dst

#define NEG_INF (-3.0e38f)

// packed fp32x2 helpers (Blackwell dual-rate fp32 path; only reachable via PTX)
__device__ __forceinline__ void ffma2(unsigned long long& d, unsigned long long a, unsigned long long b) {
    asm("fma.rn.f32x2 %0, %1, %2, %0;" : "+l"(d) : "l"(a), "l"(b));
}
__device__ __forceinline__ unsigned long long pack2(float x, float y) {
    unsigned long long r;
    asm("mov.b64 %0, {%1, %2};" : "=l"(r) : "f"(x), "f"(y));
    return r;
}
__device__ __forceinline__ float2 unpack2(unsigned long long v) {
    float2 r;
    asm("mov.b64 {%0, %1}, %2;" : "=f"(r.x), "=f"(r.y) : "l"(v));
    return r;
}

// ---------------- CSR build ----------------
__global__ void k_zero_rowptr() {
    int i = blockIdx.x * blockDim.x + threadIdx.x;
    if (i <= N_NODES) g_rowptr[i] = 0;
}

__global__ void k_hist(const int* __restrict__ dst) {
    int i = blockIdx.x * blockDim.x + threadIdx.x;
    if (i < N_EDGES) atomicAdd(&g_rowptr[dst[i] + 1], 1);
}

// single-block scan; also writes wptr (= rowptr start of each node)
__global__ void k_scan() {
    __shared__ int sums[1024];
    const int TOT = N_NODES + 1;
    const int CH = (TOT + 1023) / 1024;
    int t = threadIdx.x;
    int beg = t * CH;
    int fin = beg + CH; if (fin > TOT) fin = TOT;
    int s = 0;
    for (int i = beg; i < fin; i++) s += g_rowptr[i];
    sums[t] = s;
    __syncthreads();
    for (int off = 1; off < 1024; off <<= 1) {
        int v = 0;
        if (t >= off) v = sums[t - off];
        __syncthreads();
        sums[t] += v;
        __syncthreads();
    }
    int run = (t > 0) ? sums[t - 1] : 0;
    for (int i = beg; i < fin; i++) {
        run += g_rowptr[i];
        g_rowptr[i] = run;
        if (i < N_NODES) g_wptr[i] = run;
    }
}

__global__ void k_scatter(const int* __restrict__ src, const int* __restrict__ dst) {
    int i = blockIdx.x * blockDim.x + threadIdx.x;
    if (i < N_EDGES) {
        int pos = atomicAdd(&g_wptr[dst[i]], 1);
        g_srcs[pos] = src[i];
    }
}

// ---------------- fold al/ar into W: wa[k][c] (c<8: el head c, c>=8: er head c-8) ----------------
__global__ void k_wa(const float* __restrict__ W0, const float* __restrict__ a0l, const float* __restrict__ a0r,
                     const float* __restrict__ W1, const float* __restrict__ a1l, const float* __restrict__ a1r,
                     const float* __restrict__ W2, const float* __restrict__ a2l, const float* __restrict__ a2r,
                     const float* __restrict__ W3, const float* __restrict__ a3l, const float* __restrict__ a3r) {
    int idx = blockIdx.x * blockDim.x + threadIdx.x;
    if (idx >= 4 * 128 * 16) return;
    int l = idx >> 11;
    int k = (idx >> 4) & 127;
    int c = idx & 15;
    int h = c & 7;
    const float* W = (l == 0) ? W0 : (l == 1) ? W1 : (l == 2) ? W2 : W3;
    const float* a;
    if (c < 8) a = (l == 0) ? a0l : (l == 1) ? a1l : (l == 2) ? a2l : a3l;
    else       a = (l == 0) ? a0r : (l == 1) ? a1r : (l == 2) ? a2r : a3r;
    float s = 0.f;
#pragma unroll
    for (int d = 0; d < 16; d++) s += W[k * 128 + h * 16 + d] * a[h * 16 + d];
    g_wa[l * 2048 + k * 16 + c] = s;
}

// fold al4/ar4 into W4: g_w4ext[k*12 + c] (c<10: W4 col, 10: el weight, 11: er weight)
__global__ void k_wa5(const float* __restrict__ W4, const float* __restrict__ al4, const float* __restrict__ ar4) {
    int k = blockIdx.x * blockDim.x + threadIdx.x;
    if (k >= 128) return;
    float sl = 0.f, sr = 0.f;
#pragma unroll
    for (int c = 0; c < 10; c++) {
        float w = W4[k * 10 + c];
        g_w4ext[k * 12 + c] = w;
        sl += w * al4[c];
        sr += w * ar4[c];
    }
    g_w4ext[k * 12 + 10] = sl;
    g_w4ext[k * 12 + 11] = sr;
}

// ---------------- GEMM 128x(128+16) with packed f32x2 FMA ----------------
// Block 256 threads, 64 rows/block. Thread: 4 rows x 4 adjacent col-pairs (cols 2cg+32j+{0,1}).
__global__ void __launch_bounds__(256, 2) gemm128_kernel(const float* __restrict__ in,
                                                         const float* __restrict__ W,
                                                         const float* __restrict__ wa) {
    extern __shared__ float sm[];
    float* Wsm = sm;            // 128*128 = 16384 floats
    float* hs  = sm + 16384;    // 64*128  =  8192 floats
    float* was = sm + 24576;    // 128*16  =  2048 floats
    int tid = threadIdx.x;
    int row0 = blockIdx.x * 64;

    for (int i = tid; i < 4096; i += 256)
        ((float4*)Wsm)[i] = ((const float4*)W)[i];
    for (int i = tid; i < 512; i += 256)
        ((float4*)was)[i] = ((const float4*)wa)[i];
    for (int q = tid; q < 64 * 32; q += 256) {
        int r = q >> 5, c4 = q & 31;
        int gr = row0 + r;
        float4 v = make_float4(0.f, 0.f, 0.f, 0.f);
        if (gr < N_NODES) v = ((const float4*)in)[gr * 32 + c4];
        ((float4*)hs)[q] = v;
    }
    __syncthreads();

    int cg = tid & 15;        // col-pair group: owns cols 2cg+32j+{0,1}
    int rslot = tid >> 4;     // 0..15 -> 4 rows each
    unsigned long long acc[4][4];
    float acc2[4];
#pragma unroll
    for (int i = 0; i < 4; i++) {
        acc2[i] = 0.f;
#pragma unroll
        for (int j = 0; j < 4; j++) acc[i][j] = 0ull;
    }

    for (int k4 = 0; k4 < 128; k4 += 4) {
        float4 hv[4];
#pragma unroll
        for (int i = 0; i < 4; i++)
            hv[i] = *(const float4*)&hs[(rslot * 4 + i) * 128 + k4];
#pragma unroll
        for (int kk = 0; kk < 4; kk++) {
            unsigned long long wpk[4];
#pragma unroll
            for (int j = 0; j < 4; j++)
                wpk[j] = *(const unsigned long long*)&Wsm[(k4 + kk) * 128 + 2 * cg + 32 * j];
            float wav = was[(k4 + kk) * 16 + cg];
#pragma unroll
            for (int i = 0; i < 4; i++) {
                float hvv = (kk == 0) ? hv[i].x : (kk == 1) ? hv[i].y : (kk == 2) ? hv[i].z : hv[i].w;
                unsigned long long hd = pack2(hvv, hvv);
#pragma unroll
                for (int j = 0; j < 4; j++) ffma2(acc[i][j], hd, wpk[j]);
                acc2[i] = fmaf(hvv, wav, acc2[i]);
            }
        }
    }
#pragma unroll
    for (int i = 0; i < 4; i++) {
        int r = row0 + rslot * 4 + i;
        if (r < N_NODES) {
#pragma unroll
            for (int j = 0; j < 4; j++) {
                float2 v = unpack2(acc[i][j]);
                *(float2*)&g_feat[r * 128 + 2 * cg + 32 * j] = v;
            }
            if (cg < 8) g_el[r * 8 + cg] = acc2[i];
            else        g_er[r * 8 + cg - 8] = acc2[i];
        }
    }
}

// ---------------- per-dst softmax aggregation (8 heads, 128 dims) ----------------
// One warp per destination node. Lane owns 4 output dims of head hq = lane>>2.
__global__ void __launch_bounds__(256) aggregate_kernel(int activate) {
    int warp = (blockIdx.x * blockDim.x + threadIdx.x) >> 5;
    int lane = threadIdx.x & 31;
    if (warp >= N_NODES) return;
    int n = warp;
    int start = g_rowptr[n], end = g_rowptr[n + 1];
    if (start == end) {
        float4 z = make_float4(0.f, 0.f, 0.f, 0.f);
        *(float4*)&g_hbuf[n * 128 + lane * 4] = z;
        return;
    }
    int h8 = lane & 7;
    int hq = lane >> 2;
    float erv = g_er[n * HEADS + h8];

    // pass 1: per-head max (4 edges x 8 heads per iteration); lane covers head h8
    float mx = NEG_INF;
    for (int base = start; base < end; base += 4) {
        int j = base + (lane >> 3);
        float v = NEG_INF;
        if (j < end) {
            int s = g_srcs[j];
            float e = g_el[s * HEADS + h8] + erv;
            v = (e >= 0.f) ? e : 0.2f * e;
        }
        v = fmaxf(v, __shfl_xor_sync(0xffffffffu, v, 8));
        v = fmaxf(v, __shfl_xor_sync(0xffffffffu, v, 16));
        mx = fmaxf(mx, v);
    }
    // switch to my accumulation head hq: grab its max, load its er
    float mx2 = __shfl_sync(0xffffffffu, mx, hq);
    float erv2 = g_er[n * HEADS + hq];

    // pass 2: shfl-free — each lane computes its own head's exp locally; 4x unrolled
    float dn = 0.f;
    float4 acc = make_float4(0.f, 0.f, 0.f, 0.f);
    int j = start;
    for (; j + 3 < end; j += 4) {
        int s0 = g_srcs[j];
        int s1 = g_srcs[j + 1];
        int s2 = g_srcs[j + 2];
        int s3 = g_srcs[j + 3];
        float e0 = g_el[s0 * HEADS + hq] + erv2;
        float e1 = g_el[s1 * HEADS + hq] + erv2;
        float e2 = g_el[s2 * HEADS + hq] + erv2;
        float e3 = g_el[s3 * HEADS + hq] + erv2;
        e0 = (e0 >= 0.f) ? e0 : 0.2f * e0;
        e1 = (e1 >= 0.f) ? e1 : 0.2f * e1;
        e2 = (e2 >= 0.f) ? e2 : 0.2f * e2;
        e3 = (e3 >= 0.f) ? e3 : 0.2f * e3;
        float ex0 = __expf(e0 - mx2);
        float ex1 = __expf(e1 - mx2);
        float ex2 = __expf(e2 - mx2);
        float ex3 = __expf(e3 - mx2);
        dn += (ex0 + ex1) + (ex2 + ex3);
        float4 f0 = *(const float4*)&g_feat[s0 * 128 + lane * 4];
        float4 f1 = *(const float4*)&g_feat[s1 * 128 + lane * 4];
        float4 f2 = *(const float4*)&g_feat[s2 * 128 + lane * 4];
        float4 f3 = *(const float4*)&g_feat[s3 * 128 + lane * 4];
        acc.x = fmaf(ex0, f0.x, acc.x); acc.y = fmaf(ex0, f0.y, acc.y);
        acc.z = fmaf(ex0, f0.z, acc.z); acc.w = fmaf(ex0, f0.w, acc.w);
        acc.x = fmaf(ex1, f1.x, acc.x); acc.y = fmaf(ex1, f1.y, acc.y);
        acc.z = fmaf(ex1, f1.z, acc.z); acc.w = fmaf(ex1, f1.w, acc.w);
        acc.x = fmaf(ex2, f2.x, acc.x); acc.y = fmaf(ex2, f2.y, acc.y);
        acc.z = fmaf(ex2, f2.z, acc.z); acc.w = fmaf(ex2, f2.w, acc.w);
        acc.x = fmaf(ex3, f3.x, acc.x); acc.y = fmaf(ex3, f3.y, acc.y);
        acc.z = fmaf(ex3, f3.z, acc.z); acc.w = fmaf(ex3, f3.w, acc.w);
    }
    for (; j < end; j++) {
        int s0 = g_srcs[j];
        float e0 = g_el[s0 * HEADS + hq] + erv2;
        e0 = (e0 >= 0.f) ? e0 : 0.2f * e0;
        float ex0 = __expf(e0 - mx2);
        dn += ex0;
        float4 f0 = *(const float4*)&g_feat[s0 * 128 + lane * 4];
        acc.x = fmaf(ex0, f0.x, acc.x); acc.y = fmaf(ex0, f0.y, acc.y);
        acc.z = fmaf(ex0, f0.z, acc.z); acc.w = fmaf(ex0, f0.w, acc.w);
    }
    float inv = 1.0f / dn;
    float4 r;
    r.x = acc.x * inv; r.y = acc.y * inv; r.z = acc.z * inv; r.w = acc.w * inv;
    if (activate) {
        r.x = (r.x > 0.f) ? r.x : expm1f(r.x);
        r.y = (r.y > 0.f) ? r.y : expm1f(r.y);
        r.z = (r.z > 0.f) ? r.z : expm1f(r.z);
        r.w = (r.w > 0.f) ? r.w : expm1f(r.w);
    }
    *(float4*)&g_hbuf[n * 128 + lane * 4] = r;
}

// ---------------- layer 4: 128 -> 12 GEMM (feat5 + fused el5/er5) ----------------
__global__ void __launch_bounds__(384) gemm5_kernel() {
    __shared__ float Ws[128 * 12];
    __shared__ float hs[32 * 128];
    int tid = threadIdx.x;
    int n0 = blockIdx.x * 32;
    for (int i = tid; i < 128 * 12; i += 384) Ws[i] = g_w4ext[i];
    for (int i = tid; i < 4096; i += 384) {
        int gr = n0 + (i >> 7);
        hs[i] = (gr < N_NODES) ? g_hbuf[gr * 128 + (i & 127)] : 0.f;
    }
    __syncthreads();
    int nl = tid / 12, c = tid - nl * 12;
    if (nl >= 32) return;
    int n = n0 + nl;
    if (n >= N_NODES) return;
    float a = 0.f;
#pragma unroll 8
    for (int k = 0; k < 128; k++) a = fmaf(hs[nl * 128 + k], Ws[k * 12 + c], a);
    if (c < 10)      g_feat5[n * 10 + c] = a;
    else if (c == 10) g_el5[n] = a;
    else             g_er5[n] = a;
}

// ---------------- layer 4 aggregation (1 head, 10 dims) -> d_out ----------------
__global__ void __launch_bounds__(256) agg5_kernel(float* __restrict__ out) {
    int warp = (blockIdx.x * blockDim.x + threadIdx.x) >> 5;
    int lane = threadIdx.x & 31;
    if (warp >= N_NODES) return;
    int n = warp;
    int start = g_rowptr[n], end = g_rowptr[n + 1];
    if (start == end) {
        if (lane < 10) out[n * 10 + lane] = 0.f;
        return;
    }
    float ern = g_er5[n];
    float mx = NEG_INF;
    for (int base = start; base < end; base += 32) {
        int j = base + lane;
        float v = NEG_INF;
        if (j < end) {
            int s = g_srcs[j];
            float e = g_el5[s] + ern;
            v = (e >= 0.f) ? e : 0.2f * e;
        }
        mx = fmaxf(mx, v);
    }
#pragma unroll
    for (int off = 16; off >= 1; off >>= 1) mx = fmaxf(mx, __shfl_xor_sync(0xffffffffu, mx, off));

    float dn = 0.f;
    float acc[10];
#pragma unroll
    for (int c = 0; c < 10; c++) acc[c] = 0.f;
    for (int base = start; base < end; base += 32) {
        int j = base + lane;
        if (j < end) {
            int s = g_srcs[j];
            float e = g_el5[s] + ern;
            e = (e >= 0.f) ? e : 0.2f * e;
            float ex = __expf(e - mx);
            dn += ex;
#pragma unroll
            for (int c = 0; c < 10; c++) acc[c] = fmaf(ex, g_feat5[s * 10 + c], acc[c]);
        }
    }
#pragma unroll
    for (int off = 16; off >= 1; off >>= 1) dn += __shfl_xor_sync(0xffffffffu, dn, off);
    float res = 0.f;
#pragma unroll
    for (int c = 0; c < 10; c++) {
        float t = acc[c];
#pragma unroll
        for (int off = 16; off >= 1; off >>= 1) t += __shfl_xor_sync(0xffffffffu, t, off);
        if (lane == c) res = t;
    }
    if (lane < 10) out[n * 10 + lane] = res / dn;
}

// ---------------- launch ----------------
extern "C" void kernel_launch(void* const* d_in, const int* in_sizes, int n_in,
                              void* d_out, int out_size) {
    const float* h   = (const float*)d_in[0];
    const int*   src = (const int*)d_in[1];
    const int*   dst = (const int*)d_in[2];
    const float* W[5]  = {(const float*)d_in[3],  (const float*)d_in[6],  (const float*)d_in[9],
                          (const float*)d_in[12], (const float*)d_in[15]};
    const float* al[5] = {(const float*)d_in[4],  (const float*)d_in[7],  (const float*)d_in[10],
                          (const float*)d_in[13], (const float*)d_in[16]};
    const float* ar[5] = {(const float*)d_in[5],  (const float*)d_in[8],  (const float*)d_in[11],
                          (const float*)d_in[14], (const float*)d_in[17]};
    float* out = (float*)d_out;

    cudaFuncSetAttribute(gemm128_kernel, cudaFuncAttributeMaxDynamicSharedMemorySize, 106496);

    void* hbuf_p = nullptr;
    cudaGetSymbolAddress(&hbuf_p, g_hbuf);
    const float* hbuf = (const float*)hbuf_p;
    void* wa_p = nullptr;
    cudaGetSymbolAddress(&wa_p, g_wa);
    const float* wa = (const float*)wa_p;

    // CSR build
    k_zero_rowptr<<<(N_NODES + 1 + 255) / 256, 256>>>();
    k_hist<<<(N_EDGES + 255) / 256, 256>>>(dst);
    k_scan<<<1, 1024>>>();
    k_scatter<<<(N_EDGES + 255) / 256, 256>>>(src, dst);

    // folded attention weights
    k_wa<<<32, 256>>>(W[0], al[0], ar[0], W[1], al[1], ar[1],
                      W[2], al[2], ar[2], W[3], al[3], ar[3]);
    k_wa5<<<1, 128>>>(W[4], al[4], ar[4]);

    const float* cur = h;
    for (int l = 0; l < 4; l++) {
        gemm128_kernel<<<(N_NODES + 63) / 64, 256, 106496>>>(cur, W[l], wa + l * 2048);
        aggregate_kernel<<<(N_NODES * 32 + 255) / 256, 256>>>(1);
        cur = hbuf;
    }
    gemm5_kernel<<<(N_NODES + 31) / 32, 384>>>();
    agg5_kernel<<<(N_NODES * 32 + 255) / 256, 256>>>(out);
}

// round 9
// speedup vs baseline: 1.4733x; 1.1124x over previous
#include <cuda_runtime.h>
#include <cuda_bf16.h>

#define N_NODES 50000
#define N_EDGES 800000
#define HEADS 8
#define HID 16
#define NCLS 10

// ---------------- scratch (device globals; no allocation) ----------------
__device__ __align__(128) float g_feat[N_NODES * 128];   // transformed features
__device__ __align__(128) float g_hbuf[N_NODES * 128];   // layer output / next input
__device__ __align__(128) float g_el[N_NODES * HEADS];
__device__ __align__(128) float g_er[N_NODES * HEADS];
__device__ __align__(128) float g_wa[4 * 128 * 16];      // folded attention weights per layer
__device__ __align__(128) float g_w4ext[128 * 12];       // W4 (10 cols) + folded al4/ar4 cols
__device__ __align__(128) float g_feat5[N_NODES * NCLS];
__device__ __align__(128) float g_el5[N_NODES];
__device__ __align__(128) float g_er5[N_NODES];
__device__ __align__(128) int   g_rowptr[N_NODES + 1];
__device__ __align__(128) int   g_wptr[N_NODES];
__device__ __align__(128) int   g_srcs[N_EDGES];         // src node id, CSR-sorted by dst

#define NEG_INF (-3.0e38f)

// packed fp32x2 helpers (Blackwell dual-rate fp32 path; only reachable via PTX)
__device__ __forceinline__ void ffma2(unsigned long long& d, unsigned long long a, unsigned long long b) {
    asm("fma.rn.f32x2 %0, %1, %2, %0;" : "+l"(d) : "l"(a), "l"(b));
}
__device__ __forceinline__ unsigned long long pack2(float x, float y) {
    unsigned long long r;
    asm("mov.b64 %0, {%1, %2};" : "=l"(r) : "f"(x), "f"(y));
    return r;
}
__device__ __forceinline__ float2 unpack2(unsigned long long v) {
    float2 r;
    asm("mov.b64 {%0, %1}, %2;" : "=f"(r.x), "=f"(r.y) : "l"(v));
    return r;
}

// ---------------- CSR build ----------------
__global__ void k_zero_rowptr() {
    int i = blockIdx.x * blockDim.x + threadIdx.x;
    if (i <= N_NODES) g_rowptr[i] = 0;
}

__global__ void k_hist(const int* __restrict__ dst) {
    int i = blockIdx.x * blockDim.x + threadIdx.x;
    if (i < N_EDGES) atomicAdd(&g_rowptr[dst[i] + 1], 1);
}

// single-block scan; also writes wptr (= rowptr start of each node)
__global__ void k_scan() {
    __shared__ int sums[1024];
    const int TOT = N_NODES + 1;
    const int CH = (TOT + 1023) / 1024;
    int t = threadIdx.x;
    int beg = t * CH;
    int fin = beg + CH; if (fin > TOT) fin = TOT;
    int s = 0;
    for (int i = beg; i < fin; i++) s += g_rowptr[i];
    sums[t] = s;
    __syncthreads();
    for (int off = 1; off < 1024; off <<= 1) {
        int v = 0;
        if (t >= off) v = sums[t - off];
        __syncthreads();
        sums[t] += v;
        __syncthreads();
    }
    int run = (t > 0) ? sums[t - 1] : 0;
    for (int i = beg; i < fin; i++) {
        run += g_rowptr[i];
        g_rowptr[i] = run;
        if (i < N_NODES) g_wptr[i] = run;
    }
}

__global__ void k_scatter(const int* __restrict__ src, const int* __restrict__ dst) {
    int i = blockIdx.x * blockDim.x + threadIdx.x;
    if (i < N_EDGES) {
        int pos = atomicAdd(&g_wptr[dst[i]], 1);
        g_srcs[pos] = src[i];
    }
}

// ---------------- fold al/ar into W: wa[k][c] (c<8: el head c, c>=8: er head c-8) ----------------
__global__ void k_wa(const float* __restrict__ W0, const float* __restrict__ a0l, const float* __restrict__ a0r,
                     const float* __restrict__ W1, const float* __restrict__ a1l, const float* __restrict__ a1r,
                     const float* __restrict__ W2, const float* __restrict__ a2l, const float* __restrict__ a2r,
                     const float* __restrict__ W3, const float* __restrict__ a3l, const float* __restrict__ a3r) {
    int idx = blockIdx.x * blockDim.x + threadIdx.x;
    if (idx >= 4 * 128 * 16) return;
    int l = idx >> 11;
    int k = (idx >> 4) & 127;
    int c = idx & 15;
    int h = c & 7;
    const float* W = (l == 0) ? W0 : (l == 1) ? W1 : (l == 2) ? W2 : W3;
    const float* a;
    if (c < 8) a = (l == 0) ? a0l : (l == 1) ? a1l : (l == 2) ? a2l : a3l;
    else       a = (l == 0) ? a0r : (l == 1) ? a1r : (l == 2) ? a2r : a3r;
    float s = 0.f;
#pragma unroll
    for (int d = 0; d < 16; d++) s += W[k * 128 + h * 16 + d] * a[h * 16 + d];
    g_wa[l * 2048 + k * 16 + c] = s;
}

// fold al4/ar4 into W4: g_w4ext[k*12 + c] (c<10: W4 col, 10: el weight, 11: er weight)
__global__ void k_wa5(const float* __restrict__ W4, const float* __restrict__ al4, const float* __restrict__ ar4) {
    int k = blockIdx.x * blockDim.x + threadIdx.x;
    if (k >= 128) return;
    float sl = 0.f, sr = 0.f;
#pragma unroll
    for (int c = 0; c < 10; c++) {
        float w = W4[k * 10 + c];
        g_w4ext[k * 12 + c] = w;
        sl += w * al4[c];
        sr += w * ar4[c];
    }
    g_w4ext[k * 12 + 10] = sl;
    g_w4ext[k * 12 + 11] = sr;
}

// ---------------- GEMM 128x(128+16) with packed f32x2 FMA ----------------
__global__ void __launch_bounds__(256, 2) gemm128_kernel(const float* __restrict__ in,
                                                         const float* __restrict__ W,
                                                         const float* __restrict__ wa) {
    extern __shared__ float sm[];
    float* Wsm = sm;            // 128*128 = 16384 floats
    float* hs  = sm + 16384;    // 64*128  =  8192 floats
    float* was = sm + 24576;    // 128*16  =  2048 floats
    int tid = threadIdx.x;
    int row0 = blockIdx.x * 64;

    for (int i = tid; i < 4096; i += 256)
        ((float4*)Wsm)[i] = ((const float4*)W)[i];
    for (int i = tid; i < 512; i += 256)
        ((float4*)was)[i] = ((const float4*)wa)[i];
    for (int q = tid; q < 64 * 32; q += 256) {
        int r = q >> 5, c4 = q & 31;
        int gr = row0 + r;
        float4 v = make_float4(0.f, 0.f, 0.f, 0.f);
        if (gr < N_NODES) v = ((const float4*)in)[gr * 32 + c4];
        ((float4*)hs)[q] = v;
    }
    __syncthreads();

    int cg = tid & 15;        // col-pair group: owns cols 2cg+32j+{0,1}
    int rslot = tid >> 4;     // 0..15 -> 4 rows each
    unsigned long long acc[4][4];
    float acc2[4];
#pragma unroll
    for (int i = 0; i < 4; i++) {
        acc2[i] = 0.f;
#pragma unroll
        for (int j = 0; j < 4; j++) acc[i][j] = 0ull;
    }

    for (int k4 = 0; k4 < 128; k4 += 4) {
        float4 hv[4];
#pragma unroll
        for (int i = 0; i < 4; i++)
            hv[i] = *(const float4*)&hs[(rslot * 4 + i) * 128 + k4];
#pragma unroll
        for (int kk = 0; kk < 4; kk++) {
            unsigned long long wpk[4];
#pragma unroll
            for (int j = 0; j < 4; j++)
                wpk[j] = *(const unsigned long long*)&Wsm[(k4 + kk) * 128 + 2 * cg + 32 * j];
            float wav = was[(k4 + kk) * 16 + cg];
#pragma unroll
            for (int i = 0; i < 4; i++) {
                float hvv = (kk == 0) ? hv[i].x : (kk == 1) ? hv[i].y : (kk == 2) ? hv[i].z : hv[i].w;
                unsigned long long hd = pack2(hvv, hvv);
#pragma unroll
                for (int j = 0; j < 4; j++) ffma2(acc[i][j], hd, wpk[j]);
                acc2[i] = fmaf(hvv, wav, acc2[i]);
            }
        }
    }
#pragma unroll
    for (int i = 0; i < 4; i++) {
        int r = row0 + rslot * 4 + i;
        if (r < N_NODES) {
#pragma unroll
            for (int j = 0; j < 4; j++) {
                float2 v = unpack2(acc[i][j]);
                *(float2*)&g_feat[r * 128 + 2 * cg + 32 * j] = v;
            }
            if (cg < 8) g_el[r * 8 + cg] = acc2[i];
            else        g_er[r * 8 + cg - 8] = acc2[i];
        }
    }
}

// ---------------- per-dst online-softmax aggregation (8 heads, 128 dims) ----------------
// One warp per destination node; single pass with running (max, denom, acc).
__global__ void __launch_bounds__(256) aggregate_kernel(int activate) {
    int warp = (blockIdx.x * blockDim.x + threadIdx.x) >> 5;
    int lane = threadIdx.x & 31;
    if (warp >= N_NODES) return;
    int n = warp;
    int start = g_rowptr[n], end = g_rowptr[n + 1];
    if (start == end) {
        float4 z = make_float4(0.f, 0.f, 0.f, 0.f);
        *(float4*)&g_hbuf[n * 128 + lane * 4] = z;
        return;
    }
    int hq = lane >> 2;                 // head this lane accumulates
    float erv = g_er[n * HEADS + hq];

    float m = NEG_INF;
    float dn = 0.f;
    float4 acc = make_float4(0.f, 0.f, 0.f, 0.f);

    int j = start;
    for (; j + 1 < end; j += 2) {
        int s0 = g_srcs[j];
        int s1 = g_srcs[j + 1];
        float e0 = g_el[s0 * HEADS + hq] + erv;
        float e1 = g_el[s1 * HEADS + hq] + erv;
        e0 = (e0 >= 0.f) ? e0 : 0.2f * e0;
        e1 = (e1 >= 0.f) ? e1 : 0.2f * e1;
        float mnew = fmaxf(m, fmaxf(e0, e1));
        float sc = __expf(m - mnew);      // 0 on first iter (m=-inf), 1 if max unchanged
        float p0 = __expf(e0 - mnew);
        float p1 = __expf(e1 - mnew);
        dn = fmaf(dn, sc, p0 + p1);
        float4 f0 = *(const float4*)&g_feat[s0 * 128 + lane * 4];
        float4 f1 = *(const float4*)&g_feat[s1 * 128 + lane * 4];
        acc.x = fmaf(acc.x, sc, fmaf(p0, f0.x, p1 * f1.x));
        acc.y = fmaf(acc.y, sc, fmaf(p0, f0.y, p1 * f1.y));
        acc.z = fmaf(acc.z, sc, fmaf(p0, f0.z, p1 * f1.z));
        acc.w = fmaf(acc.w, sc, fmaf(p0, f0.w, p1 * f1.w));
        m = mnew;
    }
    if (j < end) {
        int s0 = g_srcs[j];
        float e0 = g_el[s0 * HEADS + hq] + erv;
        e0 = (e0 >= 0.f) ? e0 : 0.2f * e0;
        float mnew = fmaxf(m, e0);
        float sc = __expf(m - mnew);
        float p0 = __expf(e0 - mnew);
        dn = fmaf(dn, sc, p0);
        float4 f0 = *(const float4*)&g_feat[s0 * 128 + lane * 4];
        acc.x = fmaf(acc.x, sc, p0 * f0.x);
        acc.y = fmaf(acc.y, sc, p0 * f0.y);
        acc.z = fmaf(acc.z, sc, p0 * f0.z);
        acc.w = fmaf(acc.w, sc, p0 * f0.w);
    }
    float inv = 1.0f / dn;
    float4 r;
    r.x = acc.x * inv; r.y = acc.y * inv; r.z = acc.z * inv; r.w = acc.w * inv;
    if (activate) {
        r.x = (r.x > 0.f) ? r.x : expm1f(r.x);
        r.y = (r.y > 0.f) ? r.y : expm1f(r.y);
        r.z = (r.z > 0.f) ? r.z : expm1f(r.z);
        r.w = (r.w > 0.f) ? r.w : expm1f(r.w);
    }
    *(float4*)&g_hbuf[n * 128 + lane * 4] = r;
}

// ---------------- layer 4: 128 -> 12 GEMM (feat5 + fused el5/er5) ----------------
__global__ void __launch_bounds__(384) gemm5_kernel() {
    __shared__ float Ws[128 * 12];
    __shared__ float hs[32 * 128];
    int tid = threadIdx.x;
    int n0 = blockIdx.x * 32;
    for (int i = tid; i < 128 * 12; i += 384) Ws[i] = g_w4ext[i];
    for (int i = tid; i < 4096; i += 384) {
        int gr = n0 + (i >> 7);
        hs[i] = (gr < N_NODES) ? g_hbuf[gr * 128 + (i & 127)] : 0.f;
    }
    __syncthreads();
    int nl = tid / 12, c = tid - nl * 12;
    if (nl >= 32) return;
    int n = n0 + nl;
    if (n >= N_NODES) return;
    float a = 0.f;
#pragma unroll 8
    for (int k = 0; k < 128; k++) a = fmaf(hs[nl * 128 + k], Ws[k * 12 + c], a);
    if (c < 10)      g_feat5[n * 10 + c] = a;
    else if (c == 10) g_el5[n] = a;
    else             g_er5[n] = a;
}

// ---------------- layer 4 aggregation (1 head, 10 dims) -> d_out ----------------
__global__ void __launch_bounds__(256) agg5_kernel(float* __restrict__ out) {
    int warp = (blockIdx.x * blockDim.x + threadIdx.x) >> 5;
    int lane = threadIdx.x & 31;
    if (warp >= N_NODES) return;
    int n = warp;
    int start = g_rowptr[n], end = g_rowptr[n + 1];
    if (start == end) {
        if (lane < 10) out[n * 10 + lane] = 0.f;
        return;
    }
    float ern = g_er5[n];
    float mx = NEG_INF;
    for (int base = start; base < end; base += 32) {
        int j = base + lane;
        float v = NEG_INF;
        if (j < end) {
            int s = g_srcs[j];
            float e = g_el5[s] + ern;
            v = (e >= 0.f) ? e : 0.2f * e;
        }
        mx = fmaxf(mx, v);
    }
#pragma unroll
    for (int off = 16; off >= 1; off >>= 1) mx = fmaxf(mx, __shfl_xor_sync(0xffffffffu, mx, off));

    float dn = 0.f;
    float acc[10];
#pragma unroll
    for (int c = 0; c < 10; c++) acc[c] = 0.f;
    for (int base = start; base < end; base += 32) {
        int j = base + lane;
        if (j < end) {
            int s = g_srcs[j];
            float e = g_el5[s] + ern;
            e = (e >= 0.f) ? e : 0.2f * e;
            float ex = __expf(e - mx);
            dn += ex;
#pragma unroll
            for (int c = 0; c < 10; c++) acc[c] = fmaf(ex, g_feat5[s * 10 + c], acc[c]);
        }
    }
#pragma unroll
    for (int off = 16; off >= 1; off >>= 1) dn += __shfl_xor_sync(0xffffffffu, dn, off);
    float res = 0.f;
#pragma unroll
    for (int c = 0; c < 10; c++) {
        float t = acc[c];
#pragma unroll
        for (int off = 16; off >= 1; off >>= 1) t += __shfl_xor_sync(0xffffffffu, t, off);
        if (lane == c) res = t;
    }
    if (lane < 10) out[n * 10 + lane] = res / dn;
}

// ---------------- launch ----------------
extern "C" void kernel_launch(void* const* d_in, const int* in_sizes, int n_in,
                              void* d_out, int out_size) {
    const float* h   = (const float*)d_in[0];
    const int*   src = (const int*)d_in[1];
    const int*   dst = (const int*)d_in[2];
    const float* W[5]  = {(const float*)d_in[3],  (const float*)d_in[6],  (const float*)d_in[9],
                          (const float*)d_in[12], (const float*)d_in[15]};
    const float* al[5] = {(const float*)d_in[4],  (const float*)d_in[7],  (const float*)d_in[10],
                          (const float*)d_in[13], (const float*)d_in[16]};
    const float* ar[5] = {(const float*)d_in[5],  (const float*)d_in[8],  (const float*)d_in[11],
                          (const float*)d_in[14], (const float*)d_in[17]};
    float* out = (float*)d_out;

    // one-time resources (host-side only; GPU work identical every call)
    static cudaStream_t s2 = nullptr;
    static cudaEvent_t evFork = nullptr, evJoin = nullptr;
    if (s2 == nullptr) {
        cudaStreamCreateWithFlags(&s2, cudaStreamNonBlocking);
        cudaEventCreateWithFlags(&evFork, cudaEventDisableTiming);
        cudaEventCreateWithFlags(&evJoin, cudaEventDisableTiming);
        cudaFuncSetAttribute(gemm128_kernel, cudaFuncAttributeMaxDynamicSharedMemorySize, 106496);
    }

    void* wa_p = nullptr;
    cudaGetSymbolAddress(&wa_p, g_wa);
    const float* wa = (const float*)wa_p;
    void* hbuf_p = nullptr;
    cudaGetSymbolAddress(&hbuf_p, g_hbuf);
    const float* hbuf = (const float*)hbuf_p;

    // fork: CSR build on s2, independent of GEMM0/k_wa on main stream
    cudaEventRecord(evFork, 0);
    cudaStreamWaitEvent(s2, evFork, 0);
    k_zero_rowptr<<<(N_NODES + 1 + 255) / 256, 256, 0, s2>>>();
    k_hist<<<(N_EDGES + 255) / 256, 256, 0, s2>>>(dst);
    k_scan<<<1, 1024, 0, s2>>>();
    k_scatter<<<(N_EDGES + 255) / 256, 256, 0, s2>>>(src, dst);
    cudaEventRecord(evJoin, s2);

    // main stream: weight folding + layer-0 GEMM in parallel with CSR
    k_wa<<<32, 256>>>(W[0], al[0], ar[0], W[1], al[1], ar[1],
                      W[2], al[2], ar[2], W[3], al[3], ar[3]);
    k_wa5<<<1, 128>>>(W[4], al[4], ar[4]);
    gemm128_kernel<<<(N_NODES + 63) / 64, 256, 106496>>>(h, W[0], wa + 0 * 2048);

    // join: aggregation needs the CSR
    cudaStreamWaitEvent(0, evJoin, 0);

    aggregate_kernel<<<(N_NODES * 32 + 255) / 256, 256>>>(1);
    for (int l = 1; l < 4; l++) {
        gemm128_kernel<<<(N_NODES + 63) / 64, 256, 106496>>>(hbuf, W[l], wa + l * 2048);
        aggregate_kernel<<<(N_NODES * 32 + 255) / 256, 256>>>(1);
    }
    gemm5_kernel<<<(N_NODES + 31) / 32, 384>>>();
    agg5_kernel<<<(N_NODES * 32 + 255) / 256, 256>>>(out);
}

// round 10
// speedup vs baseline: 1.4767x; 1.0023x over previous
#include <cuda_runtime.h>
#include <cuda_bf16.h>
#include <cuda_fp16.h>

#define N_NODES 50000
#define N_EDGES 800000
#define HEADS 8
#define HID 16
#define NCLS 10

// ---------------- scratch (device globals; no allocation) ----------------
__device__ __align__(128) __half2 g_feath[N_NODES * 64]; // transformed features (fp16, col pairs)
__device__ __align__(128) float g_hbuf[N_NODES * 128];   // layer output / next input (fp32)
__device__ __align__(128) float g_el[N_NODES * HEADS];
__device__ __align__(128) float g_er[N_NODES * HEADS];
__device__ __align__(128) float g_wa[4 * 128 * 16];      // folded attention weights per layer
__device__ __align__(128) float g_w4ext[128 * 12];       // W4 (10 cols) + folded al4/ar4 cols
__device__ __align__(128) float g_feat5[N_NODES * NCLS];
__device__ __align__(128) float g_el5[N_NODES];
__device__ __align__(128) float g_er5[N_NODES];
__device__ __align__(128) int   g_rowptr[N_NODES + 1];
__device__ __align__(128) int   g_wptr[N_NODES];
__device__ __align__(128) int   g_srcs[N_EDGES];         // src node id, CSR-sorted by dst

#define NEG_INF (-3.0e38f)

// packed fp32x2 helpers (Blackwell dual-rate fp32 path; only reachable via PTX)
__device__ __forceinline__ void ffma2(unsigned long long& d, unsigned long long a, unsigned long long b) {
    asm("fma.rn.f32x2 %0, %1, %2, %0;" : "+l"(d) : "l"(a), "l"(b));
}
__device__ __forceinline__ unsigned long long pack2(float x, float y) {
    unsigned long long r;
    asm("mov.b64 %0, {%1, %2};" : "=l"(r) : "f"(x), "f"(y));
    return r;
}
__device__ __forceinline__ float2 unpack2(unsigned long long v) {
    float2 r;
    asm("mov.b64 {%0, %1}, %2;" : "=f"(r.x), "=f"(r.y) : "l"(v));
    return r;
}

// ---------------- CSR build ----------------
__global__ void k_zero_rowptr() {
    int i = blockIdx.x * blockDim.x + threadIdx.x;
    if (i <= N_NODES) g_rowptr[i] = 0;
}

__global__ void k_hist(const int* __restrict__ dst) {
    int i = blockIdx.x * blockDim.x + threadIdx.x;
    if (i < N_EDGES) atomicAdd(&g_rowptr[dst[i] + 1], 1);
}

// single-block scan; also writes wptr (= rowptr start of each node)
__global__ void k_scan() {
    __shared__ int sums[1024];
    const int TOT = N_NODES + 1;
    const int CH = (TOT + 1023) / 1024;
    int t = threadIdx.x;
    int beg = t * CH;
    int fin = beg + CH; if (fin > TOT) fin = TOT;
    int s = 0;
    for (int i = beg; i < fin; i++) s += g_rowptr[i];
    sums[t] = s;
    __syncthreads();
    for (int off = 1; off < 1024; off <<= 1) {
        int v = 0;
        if (t >= off) v = sums[t - off];
        __syncthreads();
        sums[t] += v;
        __syncthreads();
    }
    int run = (t > 0) ? sums[t - 1] : 0;
    for (int i = beg; i < fin; i++) {
        run += g_rowptr[i];
        g_rowptr[i] = run;
        if (i < N_NODES) g_wptr[i] = run;
    }
}

__global__ void k_scatter(const int* __restrict__ src, const int* __restrict__ dst) {
    int i = blockIdx.x * blockDim.x + threadIdx.x;
    if (i < N_EDGES) {
        int pos = atomicAdd(&g_wptr[dst[i]], 1);
        g_srcs[pos] = src[i];
    }
}

// ---------------- fold al/ar into W: wa[k][c] (c<8: el head c, c>=8: er head c-8) ----------------
__global__ void k_wa(const float* __restrict__ W0, const float* __restrict__ a0l, const float* __restrict__ a0r,
                     const float* __restrict__ W1, const float* __restrict__ a1l, const float* __restrict__ a1r,
                     const float* __restrict__ W2, const float* __restrict__ a2l, const float* __restrict__ a2r,
                     const float* __restrict__ W3, const float* __restrict__ a3l, const float* __restrict__ a3r) {
    int idx = blockIdx.x * blockDim.x + threadIdx.x;
    if (idx >= 4 * 128 * 16) return;
    int l = idx >> 11;
    int k = (idx >> 4) & 127;
    int c = idx & 15;
    int h = c & 7;
    const float* W = (l == 0) ? W0 : (l == 1) ? W1 : (l == 2) ? W2 : W3;
    const float* a;
    if (c < 8) a = (l == 0) ? a0l : (l == 1) ? a1l : (l == 2) ? a2l : a3l;
    else       a = (l == 0) ? a0r : (l == 1) ? a1r : (l == 2) ? a2r : a3r;
    float s = 0.f;
#pragma unroll
    for (int d = 0; d < 16; d++) s += W[k * 128 + h * 16 + d] * a[h * 16 + d];
    g_wa[l * 2048 + k * 16 + c] = s;
}

// fold al4/ar4 into W4: g_w4ext[k*12 + c] (c<10: W4 col, 10: el weight, 11: er weight)
__global__ void k_wa5(const float* __restrict__ W4, const float* __restrict__ al4, const float* __restrict__ ar4) {
    int k = blockIdx.x * blockDim.x + threadIdx.x;
    if (k >= 128) return;
    float sl = 0.f, sr = 0.f;
#pragma unroll
    for (int c = 0; c < 10; c++) {
        float w = W4[k * 10 + c];
        g_w4ext[k * 12 + c] = w;
        sl += w * al4[c];
        sr += w * ar4[c];
    }
    g_w4ext[k * 12 + 10] = sl;
    g_w4ext[k * 12 + 11] = sr;
}

// ---------------- GEMM 128x(128+16) with packed f32x2 FMA; fp16 feature epilogue ----------------
__global__ void __launch_bounds__(256, 2) gemm128_kernel(const float* __restrict__ in,
                                                         const float* __restrict__ W,
                                                         const float* __restrict__ wa) {
    extern __shared__ float sm[];
    float* Wsm = sm;            // 128*128 = 16384 floats
    float* hs  = sm + 16384;    // 64*128  =  8192 floats
    float* was = sm + 24576;    // 128*16  =  2048 floats
    int tid = threadIdx.x;
    int row0 = blockIdx.x * 64;

    for (int i = tid; i < 4096; i += 256)
        ((float4*)Wsm)[i] = ((const float4*)W)[i];
    for (int i = tid; i < 512; i += 256)
        ((float4*)was)[i] = ((const float4*)wa)[i];
    for (int q = tid; q < 64 * 32; q += 256) {
        int r = q >> 5, c4 = q & 31;
        int gr = row0 + r;
        float4 v = make_float4(0.f, 0.f, 0.f, 0.f);
        if (gr < N_NODES) v = ((const float4*)in)[gr * 32 + c4];
        ((float4*)hs)[q] = v;
    }
    __syncthreads();

    int cg = tid & 15;        // col-pair group: owns col pairs cg+16j (cols 2cg+32j+{0,1})
    int rslot = tid >> 4;     // 0..15 -> 4 rows each
    unsigned long long acc[4][4];
    float acc2[4];
#pragma unroll
    for (int i = 0; i < 4; i++) {
        acc2[i] = 0.f;
#pragma unroll
        for (int j = 0; j < 4; j++) acc[i][j] = 0ull;
    }

    for (int k4 = 0; k4 < 128; k4 += 4) {
        float4 hv[4];
#pragma unroll
        for (int i = 0; i < 4; i++)
            hv[i] = *(const float4*)&hs[(rslot * 4 + i) * 128 + k4];
#pragma unroll
        for (int kk = 0; kk < 4; kk++) {
            unsigned long long wpk[4];
#pragma unroll
            for (int j = 0; j < 4; j++)
                wpk[j] = *(const unsigned long long*)&Wsm[(k4 + kk) * 128 + 2 * cg + 32 * j];
            float wav = was[(k4 + kk) * 16 + cg];
#pragma unroll
            for (int i = 0; i < 4; i++) {
                float hvv = (kk == 0) ? hv[i].x : (kk == 1) ? hv[i].y : (kk == 2) ? hv[i].z : hv[i].w;
                unsigned long long hd = pack2(hvv, hvv);
#pragma unroll
                for (int j = 0; j < 4; j++) ffma2(acc[i][j], hd, wpk[j]);
                acc2[i] = fmaf(hvv, wav, acc2[i]);
            }
        }
    }
#pragma unroll
    for (int i = 0; i < 4; i++) {
        int r = row0 + rslot * 4 + i;
        if (r < N_NODES) {
#pragma unroll
            for (int j = 0; j < 4; j++) {
                float2 v = unpack2(acc[i][j]);
                g_feath[r * 64 + cg + 16 * j] = __float22half2_rn(v);
            }
            if (cg < 8) g_el[r * 8 + cg] = acc2[i];
            else        g_er[r * 8 + cg - 8] = acc2[i];
        }
    }
}

// ---------------- per-dst online-softmax aggregation (8 heads, 128 dims, fp16 gather) ----------------
// One warp per destination node; single pass with running (max, denom, acc).
__global__ void __launch_bounds__(256) aggregate_kernel(int activate) {
    int warp = (blockIdx.x * blockDim.x + threadIdx.x) >> 5;
    int lane = threadIdx.x & 31;
    if (warp >= N_NODES) return;
    int n = warp;
    int start = g_rowptr[n], end = g_rowptr[n + 1];
    if (start == end) {
        float4 z = make_float4(0.f, 0.f, 0.f, 0.f);
        *(float4*)&g_hbuf[n * 128 + lane * 4] = z;
        return;
    }
    int hq = lane >> 2;                 // head this lane accumulates
    float erv = g_er[n * HEADS + hq];

    float m = NEG_INF;
    float dn = 0.f;
    float4 acc = make_float4(0.f, 0.f, 0.f, 0.f);

    int j = start;
    for (; j + 1 < end; j += 2) {
        int s0 = g_srcs[j];
        int s1 = g_srcs[j + 1];
        float e0 = g_el[s0 * HEADS + hq] + erv;
        float e1 = g_el[s1 * HEADS + hq] + erv;
        e0 = (e0 >= 0.f) ? e0 : 0.2f * e0;
        e1 = (e1 >= 0.f) ? e1 : 0.2f * e1;
        float mnew = fmaxf(m, fmaxf(e0, e1));
        float sc = __expf(m - mnew);      // 0 on first iter (m=-inf), 1 if max unchanged
        float p0 = __expf(e0 - mnew);
        float p1 = __expf(e1 - mnew);
        dn = fmaf(dn, sc, p0 + p1);
        // fp16 feature row: lane owns pairs 2*lane, 2*lane+1 (dims 4*lane..4*lane+3)
        __half2 q0a = g_feath[s0 * 64 + lane * 2];
        __half2 q0b = g_feath[s0 * 64 + lane * 2 + 1];
        __half2 q1a = g_feath[s1 * 64 + lane * 2];
        __half2 q1b = g_feath[s1 * 64 + lane * 2 + 1];
        float2 f0a = __half22float2(q0a), f0b = __half22float2(q0b);
        float2 f1a = __half22float2(q1a), f1b = __half22float2(q1b);
        acc.x = fmaf(acc.x, sc, fmaf(p0, f0a.x, p1 * f1a.x));
        acc.y = fmaf(acc.y, sc, fmaf(p0, f0a.y, p1 * f1a.y));
        acc.z = fmaf(acc.z, sc, fmaf(p0, f0b.x, p1 * f1b.x));
        acc.w = fmaf(acc.w, sc, fmaf(p0, f0b.y, p1 * f1b.y));
        m = mnew;
    }
    if (j < end) {
        int s0 = g_srcs[j];
        float e0 = g_el[s0 * HEADS + hq] + erv;
        e0 = (e0 >= 0.f) ? e0 : 0.2f * e0;
        float mnew = fmaxf(m, e0);
        float sc = __expf(m - mnew);
        float p0 = __expf(e0 - mnew);
        dn = fmaf(dn, sc, p0);
        __half2 q0a = g_feath[s0 * 64 + lane * 2];
        __half2 q0b = g_feath[s0 * 64 + lane * 2 + 1];
        float2 f0a = __half22float2(q0a), f0b = __half22float2(q0b);
        acc.x = fmaf(acc.x, sc, p0 * f0a.x);
        acc.y = fmaf(acc.y, sc, p0 * f0a.y);
        acc.z = fmaf(acc.z, sc, p0 * f0b.x);
        acc.w = fmaf(acc.w, sc, p0 * f0b.y);
    }
    float inv = 1.0f / dn;
    float4 r;
    r.x = acc.x * inv; r.y = acc.y * inv; r.z = acc.z * inv; r.w = acc.w * inv;
    if (activate) {
        r.x = (r.x > 0.f) ? r.x : expm1f(r.x);
        r.y = (r.y > 0.f) ? r.y : expm1f(r.y);
        r.z = (r.z > 0.f) ? r.z : expm1f(r.z);
        r.w = (r.w > 0.f) ? r.w : expm1f(r.w);
    }
    *(float4*)&g_hbuf[n * 128 + lane * 4] = r;
}

// ---------------- layer 4: 128 -> 12 GEMM (feat5 + fused el5/er5) ----------------
__global__ void __launch_bounds__(384) gemm5_kernel() {
    __shared__ float Ws[128 * 12];
    __shared__ float hs[32 * 128];
    int tid = threadIdx.x;
    int n0 = blockIdx.x * 32;
    for (int i = tid; i < 128 * 12; i += 384) Ws[i] = g_w4ext[i];
    for (int i = tid; i < 4096; i += 384) {
        int gr = n0 + (i >> 7);
        hs[i] = (gr < N_NODES) ? g_hbuf[gr * 128 + (i & 127)] : 0.f;
    }
    __syncthreads();
    int nl = tid / 12, c = tid - nl * 12;
    if (nl >= 32) return;
    int n = n0 + nl;
    if (n >= N_NODES) return;
    float a = 0.f;
#pragma unroll 8
    for (int k = 0; k < 128; k++) a = fmaf(hs[nl * 128 + k], Ws[k * 12 + c], a);
    if (c < 10)      g_feat5[n * 10 + c] = a;
    else if (c == 10) g_el5[n] = a;
    else             g_er5[n] = a;
}

// ---------------- layer 4 aggregation (1 head, 10 dims) -> d_out ----------------
__global__ void __launch_bounds__(256) agg5_kernel(float* __restrict__ out) {
    int warp = (blockIdx.x * blockDim.x + threadIdx.x) >> 5;
    int lane = threadIdx.x & 31;
    if (warp >= N_NODES) return;
    int n = warp;
    int start = g_rowptr[n], end = g_rowptr[n + 1];
    if (start == end) {
        if (lane < 10) out[n * 10 + lane] = 0.f;
        return;
    }
    float ern = g_er5[n];
    float mx = NEG_INF;
    for (int base = start; base < end; base += 32) {
        int j = base + lane;
        float v = NEG_INF;
        if (j < end) {
            int s = g_srcs[j];
            float e = g_el5[s] + ern;
            v = (e >= 0.f) ? e : 0.2f * e;
        }
        mx = fmaxf(mx, v);
    }
#pragma unroll
    for (int off = 16; off >= 1; off >>= 1) mx = fmaxf(mx, __shfl_xor_sync(0xffffffffu, mx, off));

    float dn = 0.f;
    float acc[10];
#pragma unroll
    for (int c = 0; c < 10; c++) acc[c] = 0.f;
    for (int base = start; base < end; base += 32) {
        int j = base + lane;
        if (j < end) {
            int s = g_srcs[j];
            float e = g_el5[s] + ern;
            e = (e >= 0.f) ? e : 0.2f * e;
            float ex = __expf(e - mx);
            dn += ex;
#pragma unroll
            for (int c = 0; c < 10; c++) acc[c] = fmaf(ex, g_feat5[s * 10 + c], acc[c]);
        }
    }
#pragma unroll
    for (int off = 16; off >= 1; off >>= 1) dn += __shfl_xor_sync(0xffffffffu, dn, off);
    float res = 0.f;
#pragma unroll
    for (int c = 0; c < 10; c++) {
        float t = acc[c];
#pragma unroll
        for (int off = 16; off >= 1; off >>= 1) t += __shfl_xor_sync(0xffffffffu, t, off);
        if (lane == c) res = t;
    }
    if (lane < 10) out[n * 10 + lane] = res / dn;
}

// ---------------- launch ----------------
extern "C" void kernel_launch(void* const* d_in, const int* in_sizes, int n_in,
                              void* d_out, int out_size) {
    const float* h   = (const float*)d_in[0];
    const int*   src = (const int*)d_in[1];
    const int*   dst = (const int*)d_in[2];
    const float* W[5]  = {(const float*)d_in[3],  (const float*)d_in[6],  (const float*)d_in[9],
                          (const float*)d_in[12], (const float*)d_in[15]};
    const float* al[5] = {(const float*)d_in[4],  (const float*)d_in[7],  (const float*)d_in[10],
                          (const float*)d_in[13], (const float*)d_in[16]};
    const float* ar[5] = {(const float*)d_in[5],  (const float*)d_in[8],  (const float*)d_in[11],
                          (const float*)d_in[14], (const float*)d_in[17]};
    float* out = (float*)d_out;

    // one-time resources (host-side only; GPU work identical every call)
    static cudaStream_t s2 = nullptr;
    static cudaEvent_t evFork = nullptr, evJoin = nullptr;
    if (s2 == nullptr) {
        cudaStreamCreateWithFlags(&s2, cudaStreamNonBlocking);
        cudaEventCreateWithFlags(&evFork, cudaEventDisableTiming);
        cudaEventCreateWithFlags(&evJoin, cudaEventDisableTiming);
        cudaFuncSetAttribute(gemm128_kernel, cudaFuncAttributeMaxDynamicSharedMemorySize, 106496);
    }

    void* wa_p = nullptr;
    cudaGetSymbolAddress(&wa_p, g_wa);
    const float* wa = (const float*)wa_p;
    void* hbuf_p = nullptr;
    cudaGetSymbolAddress(&hbuf_p, g_hbuf);
    const float* hbuf = (const float*)hbuf_p;

    // fork: CSR build on s2, independent of GEMM0/k_wa on main stream
    cudaEventRecord(evFork, 0);
    cudaStreamWaitEvent(s2, evFork, 0);
    k_zero_rowptr<<<(N_NODES + 1 + 255) / 256, 256, 0, s2>>>();
    k_hist<<<(N_EDGES + 255) / 256, 256, 0, s2>>>(dst);
    k_scan<<<1, 1024, 0, s2>>>();
    k_scatter<<<(N_EDGES + 255) / 256, 256, 0, s2>>>(src, dst);
    cudaEventRecord(evJoin, s2);

    // main stream: weight folding + layer-0 GEMM in parallel with CSR
    k_wa<<<32, 256>>>(W[0], al[0], ar[0], W[1], al[1], ar[1],
                      W[2], al[2], ar[2], W[3], al[3], ar[3]);
    k_wa5<<<1, 128>>>(W[4], al[4], ar[4]);
    gemm128_kernel<<<(N_NODES + 63) / 64, 256, 106496>>>(h, W[0], wa + 0 * 2048);

    // join: aggregation needs the CSR
    cudaStreamWaitEvent(0, evJoin, 0);

    aggregate_kernel<<<(N_NODES * 32 + 255) / 256, 256>>>(1);
    for (int l = 1; l < 4; l++) {
        gemm128_kernel<<<(N_NODES + 63) / 64, 256, 106496>>>(hbuf, W[l], wa + l * 2048);
        aggregate_kernel<<<(N_NODES * 32 + 255) / 256, 256>>>(1);
    }
    gemm5_kernel<<<(N_NODES + 31) / 32, 384>>>();
    agg5_kernel<<<(N_NODES * 32 + 255) / 256, 256>>>(out);
}

// round 13
// speedup vs baseline: 1.6986x; 1.1503x over previous
#include <cuda_runtime.h>
#include <cuda_bf16.h>
#include <cuda_fp16.h>
#include <stdint.h>

typedef unsigned int u32;

#define N_NODES 50000
#define N_EDGES 800000
#define HEADS 8
#define HID 16
#define NCLS 10

// ---------------- scratch (device globals; no allocation) ----------------
__device__ __align__(128) __half2 g_feath[N_NODES * 64]; // transformed features (fp16, col pairs)
__device__ __align__(128) float g_hbuf[N_NODES * 128];   // layer output / next input (fp32)
__device__ __align__(128) float g_el[N_NODES * HEADS];
__device__ __align__(128) float g_er[N_NODES * HEADS];
__device__ __align__(128) float g_wa[4 * 128 * 16];      // folded attention weights per layer
__device__ __align__(128) float g_w4ext[128 * 12];       // W4 (10 cols) + folded al4/ar4 cols
__device__ __align__(128) float g_feat5[N_NODES * NCLS];
__device__ __align__(128) float g_el5[N_NODES];
__device__ __align__(128) float g_er5[N_NODES];
__device__ __align__(128) int   g_rowptr[N_NODES + 1];
__device__ __align__(128) int   g_wptr[N_NODES];
__device__ __align__(128) int   g_srcs[N_EDGES];         // src node id, CSR-sorted by dst

#define NEG_INF (-3.0e38f)

// ---------------- tf32 mma helpers ----------------
__device__ __forceinline__ u32 f2tf32(float f) {
    u32 r;
    asm("cvt.rna.tf32.f32 %0, %1;" : "=r"(r) : "f"(f));
    return r;
}
__device__ __forceinline__ void mma_tf32(float* c,
                                         u32 a0, u32 a1, u32 a2, u32 a3,
                                         u32 b0, u32 b1) {
    asm("mma.sync.aligned.m16n8k8.row.col.f32.tf32.tf32.f32 "
        "{%0,%1,%2,%3},{%4,%5,%6,%7},{%8,%9},{%0,%1,%2,%3};"
        : "+f"(c[0]), "+f"(c[1]), "+f"(c[2]), "+f"(c[3])
        : "r"(a0), "r"(a1), "r"(a2), "r"(a3), "r"(b0), "r"(b1));
}

// ---------------- CSR build ----------------
__global__ void k_zero_rowptr() {
    int i = blockIdx.x * blockDim.x + threadIdx.x;
    if (i <= N_NODES) g_rowptr[i] = 0;
}

__global__ void k_hist(const int* __restrict__ dst) {
    int i = blockIdx.x * blockDim.x + threadIdx.x;
    if (i < N_EDGES) atomicAdd(&g_rowptr[dst[i] + 1], 1);
}

// single-block scan; also writes wptr (= rowptr start of each node)
__global__ void k_scan() {
    __shared__ int sums[1024];
    const int TOT = N_NODES + 1;
    const int CH = (TOT + 1023) / 1024;
    int t = threadIdx.x;
    int beg = t * CH;
    int fin = beg + CH; if (fin > TOT) fin = TOT;
    int s = 0;
    for (int i = beg; i < fin; i++) s += g_rowptr[i];
    sums[t] = s;
    __syncthreads();
    for (int off = 1; off < 1024; off <<= 1) {
        int v = 0;
        if (t >= off) v = sums[t - off];
        __syncthreads();
        sums[t] += v;
        __syncthreads();
    }
    int run = (t > 0) ? sums[t - 1] : 0;
    for (int i = beg; i < fin; i++) {
        run += g_rowptr[i];
        g_rowptr[i] = run;
        if (i < N_NODES) g_wptr[i] = run;
    }
}

__global__ void k_scatter(const int* __restrict__ src, const int* __restrict__ dst) {
    int i = blockIdx.x * blockDim.x + threadIdx.x;
    if (i < N_EDGES) {
        int pos = atomicAdd(&g_wptr[dst[i]], 1);
        g_srcs[pos] = src[i];
    }
}

// ---------------- fold al/ar into W: wa[k][c] (c<8: el head c, c>=8: er head c-8) ----------------
__global__ void k_wa(const float* __restrict__ W0, const float* __restrict__ a0l, const float* __restrict__ a0r,
                     const float* __restrict__ W1, const float* __restrict__ a1l, const float* __restrict__ a1r,
                     const float* __restrict__ W2, const float* __restrict__ a2l, const float* __restrict__ a2r,
                     const float* __restrict__ W3, const float* __restrict__ a3l, const float* __restrict__ a3r) {
    int idx = blockIdx.x * blockDim.x + threadIdx.x;
    if (idx >= 4 * 128 * 16) return;
    int l = idx >> 11;
    int k = (idx >> 4) & 127;
    int c = idx & 15;
    int h = c & 7;
    const float* W = (l == 0) ? W0 : (l == 1) ? W1 : (l == 2) ? W2 : W3;
    const float* a;
    if (c < 8) a = (l == 0) ? a0l : (l == 1) ? a1l : (l == 2) ? a2l : a3l;
    else       a = (l == 0) ? a0r : (l == 1) ? a1r : (l == 2) ? a2r : a3r;
    float s = 0.f;
#pragma unroll
    for (int d = 0; d < 16; d++) s += W[k * 128 + h * 16 + d] * a[h * 16 + d];
    g_wa[l * 2048 + k * 16 + c] = s;
}

// fold al4/ar4 into W4: g_w4ext[k*12 + c] (c<10: W4 col, 10: el weight, 11: er weight)
__global__ void k_wa5(const float* __restrict__ W4, const float* __restrict__ al4, const float* __restrict__ ar4) {
    int k = blockIdx.x * blockDim.x + threadIdx.x;
    if (k >= 128) return;
    float sl = 0.f, sr = 0.f;
#pragma unroll
    for (int c = 0; c < 10; c++) {
        float w = W4[k * 10 + c];
        g_w4ext[k * 12 + c] = w;
        sl += w * al4[c];
        sr += w * ar4[c];
    }
    g_w4ext[k * 12 + 10] = sl;
    g_w4ext[k * 12 + 11] = sr;
}

// ---------------- GEMM 128x(128+16) via tf32 mma.sync ----------------
// Block 256 threads (8 warps), 64 rows. B matrix = [W | wa] (144 cols) in one
// padded smem tile (stride 152 words -> conflict-free B-frag banks).
// Warp w: rows (w&3)*16..+15, n8-tiles (w>>2)*9..+8 (18 tiles = 144 cols).
// Tiles 0..15 -> feat (fp16 epilogue); tile 16 -> el, tile 17 -> er (fp32).
#define WB_STRIDE 152
#define HS_STRIDE 132
__global__ void __launch_bounds__(256, 2) gemm128_kernel(const float* __restrict__ in,
                                                         const float* __restrict__ W,
                                                         const float* __restrict__ wa) {
    extern __shared__ u32 smu[];
    u32* WBs = smu;                       // 128 x 152
    u32* hss = smu + 128 * WB_STRIDE;     // 64 x 132
    int tid = threadIdx.x;
    int row0 = blockIdx.x * 64;

    // fill W cols 0..127 (tf32)
    for (int i = tid; i < 4096; i += 256) {
        int k = i >> 5, n4 = i & 31;
        float4 v = ((const float4*)W)[i];
        uint4 u = make_uint4(f2tf32(v.x), f2tf32(v.y), f2tf32(v.z), f2tf32(v.w));
        *(uint4*)&WBs[k * WB_STRIDE + n4 * 4] = u;
    }
    // fill wa cols 128..143 (tf32)
    for (int i = tid; i < 512; i += 256) {
        int k = i >> 2, c4 = i & 3;
        float4 v = ((const float4*)wa)[i];
        uint4 u = make_uint4(f2tf32(v.x), f2tf32(v.y), f2tf32(v.z), f2tf32(v.w));
        *(uint4*)&WBs[k * WB_STRIDE + 128 + c4 * 4] = u;
    }
    // fill h tile (tf32)
    for (int i = tid; i < 2048; i += 256) {
        int r = i >> 5, c4 = i & 31;
        int gr = row0 + r;
        float4 v = make_float4(0.f, 0.f, 0.f, 0.f);
        if (gr < N_NODES) v = ((const float4*)in)[gr * 32 + c4];
        uint4 u = make_uint4(f2tf32(v.x), f2tf32(v.y), f2tf32(v.z), f2tf32(v.w));
        *(uint4*)&hss[r * HS_STRIDE + c4 * 4] = u;
    }
    __syncthreads();

    int lane = tid & 31;
    int w = tid >> 5;
    int rg = (w & 3) * 16;
    int tbase = (w >> 2) * 9;
    int gid = lane >> 2;   // group id 0..7
    int tig = lane & 3;    // thread-in-group 0..3

    const u32* A = hss + (rg + gid) * HS_STRIDE + tig;
    const u32* B = WBs + tig * WB_STRIDE + gid;

    float c[9][4];
#pragma unroll
    for (int t = 0; t < 9; t++) {
        c[t][0] = 0.f; c[t][1] = 0.f; c[t][2] = 0.f; c[t][3] = 0.f;
    }

    for (int ks = 0; ks < 16; ks++) {
        u32 a0 = A[ks * 8];
        u32 a1 = A[8 * HS_STRIDE + ks * 8];
        u32 a2 = A[ks * 8 + 4];
        u32 a3 = A[8 * HS_STRIDE + ks * 8 + 4];
        const u32* Bk = B + ks * 8 * WB_STRIDE;
#pragma unroll
        for (int t = 0; t < 9; t++) {
            int gt = tbase + t;
            u32 b0 = Bk[gt * 8];
            u32 b1 = Bk[4 * WB_STRIDE + gt * 8];
            mma_tf32(c[t], a0, a1, a2, a3, b0, b1);
        }
    }

    int r0 = row0 + rg + gid;
    int r1 = r0 + 8;
#pragma unroll
    for (int t = 0; t < 9; t++) {
        int gt = tbase + t;
        if (gt < 16) {
            int p = gt * 4 + tig;   // half2 pair index (cols 2p, 2p+1)
            if (r0 < N_NODES) g_feath[r0 * 64 + p] = __floats2half2_rn(c[t][0], c[t][1]);
            if (r1 < N_NODES) g_feath[r1 * 64 + p] = __floats2half2_rn(c[t][2], c[t][3]);
        } else if (gt == 16) {
            int hh = 2 * tig;
            if (r0 < N_NODES) { g_el[r0 * 8 + hh] = c[t][0]; g_el[r0 * 8 + hh + 1] = c[t][1]; }
            if (r1 < N_NODES) { g_el[r1 * 8 + hh] = c[t][2]; g_el[r1 * 8 + hh + 1] = c[t][3]; }
        } else {
            int hh = 2 * tig;
            if (r0 < N_NODES) { g_er[r0 * 8 + hh] = c[t][0]; g_er[r0 * 8 + hh + 1] = c[t][1]; }
            if (r1 < N_NODES) { g_er[r1 * 8 + hh] = c[t][2]; g_er[r1 * 8 + hh + 1] = c[t][3]; }
        }
    }
}
#define GEMM_SMEM ((128 * WB_STRIDE + 64 * HS_STRIDE) * 4)

// ---------------- per-dst online-softmax aggregation (8 heads, 128 dims, fp16 gather) ----------------
// One warp per destination node; single pass, 4 edges per iteration (MLP=4).
__global__ void __launch_bounds__(256) aggregate_kernel(int activate) {
    int warp = (blockIdx.x * blockDim.x + threadIdx.x) >> 5;
    int lane = threadIdx.x & 31;
    if (warp >= N_NODES) return;
    int n = warp;
    int start = g_rowptr[n], end = g_rowptr[n + 1];
    if (start == end) {
        float4 z = make_float4(0.f, 0.f, 0.f, 0.f);
        *(float4*)&g_hbuf[n * 128 + lane * 4] = z;
        return;
    }
    int hq = lane >> 2;                 // head this lane accumulates
    float erv = g_er[n * HEADS + hq];

    float m = NEG_INF;
    float dn = 0.f;
    float4 acc = make_float4(0.f, 0.f, 0.f, 0.f);

    int j = start;
    for (; j + 3 < end; j += 4) {
        int s0 = g_srcs[j];
        int s1 = g_srcs[j + 1];
        int s2 = g_srcs[j + 2];
        int s3 = g_srcs[j + 3];
        float e0 = g_el[s0 * HEADS + hq] + erv;
        float e1 = g_el[s1 * HEADS + hq] + erv;
        float e2 = g_el[s2 * HEADS + hq] + erv;
        float e3 = g_el[s3 * HEADS + hq] + erv;
        e0 = (e0 >= 0.f) ? e0 : 0.2f * e0;
        e1 = (e1 >= 0.f) ? e1 : 0.2f * e1;
        e2 = (e2 >= 0.f) ? e2 : 0.2f * e2;
        e3 = (e3 >= 0.f) ? e3 : 0.2f * e3;
        float mnew = fmaxf(m, fmaxf(fmaxf(e0, e1), fmaxf(e2, e3)));
        float sc = __expf(m - mnew);
        float p0 = __expf(e0 - mnew);
        float p1 = __expf(e1 - mnew);
        float p2 = __expf(e2 - mnew);
        float p3 = __expf(e3 - mnew);
        dn = fmaf(dn, sc, (p0 + p1) + (p2 + p3));
        __half2 q0a = g_feath[s0 * 64 + lane * 2], q0b = g_feath[s0 * 64 + lane * 2 + 1];
        __half2 q1a = g_feath[s1 * 64 + lane * 2], q1b = g_feath[s1 * 64 + lane * 2 + 1];
        __half2 q2a = g_feath[s2 * 64 + lane * 2], q2b = g_feath[s2 * 64 + lane * 2 + 1];
        __half2 q3a = g_feath[s3 * 64 + lane * 2], q3b = g_feath[s3 * 64 + lane * 2 + 1];
        float2 f0a = __half22float2(q0a), f0b = __half22float2(q0b);
        float2 f1a = __half22float2(q1a), f1b = __half22float2(q1b);
        float2 f2a = __half22float2(q2a), f2b = __half22float2(q2b);
        float2 f3a = __half22float2(q3a), f3b = __half22float2(q3b);
        acc.x = fmaf(acc.x, sc, fmaf(p0, f0a.x, fmaf(p1, f1a.x, fmaf(p2, f2a.x, p3 * f3a.x))));
        acc.y = fmaf(acc.y, sc, fmaf(p0, f0a.y, fmaf(p1, f1a.y, fmaf(p2, f2a.y, p3 * f3a.y))));
        acc.z = fmaf(acc.z, sc, fmaf(p0, f0b.x, fmaf(p1, f1b.x, fmaf(p2, f2b.x, p3 * f3b.x))));
        acc.w = fmaf(acc.w, sc, fmaf(p0, f0b.y, fmaf(p1, f1b.y, fmaf(p2, f2b.y, p3 * f3b.y))));
        m = mnew;
    }
    for (; j < end; j++) {
        int s0 = g_srcs[j];
        float e0 = g_el[s0 * HEADS + hq] + erv;
        e0 = (e0 >= 0.f) ? e0 : 0.2f * e0;
        float mnew = fmaxf(m, e0);
        float sc = __expf(m - mnew);
        float p0 = __expf(e0 - mnew);
        dn = fmaf(dn, sc, p0);
        __half2 q0a = g_feath[s0 * 64 + lane * 2], q0b = g_feath[s0 * 64 + lane * 2 + 1];
        float2 f0a = __half22float2(q0a), f0b = __half22float2(q0b);
        acc.x = fmaf(acc.x, sc, p0 * f0a.x);
        acc.y = fmaf(acc.y, sc, p0 * f0a.y);
        acc.z = fmaf(acc.z, sc, p0 * f0b.x);
        acc.w = fmaf(acc.w, sc, p0 * f0b.y);
        m = mnew;
    }
    float inv = 1.0f / dn;
    float4 r;
    r.x = acc.x * inv; r.y = acc.y * inv; r.z = acc.z * inv; r.w = acc.w * inv;
    if (activate) {
        r.x = (r.x > 0.f) ? r.x : expm1f(r.x);
        r.y = (r.y > 0.f) ? r.y : expm1f(r.y);
        r.z = (r.z > 0.f) ? r.z : expm1f(r.z);
        r.w = (r.w > 0.f) ? r.w : expm1f(r.w);
    }
    *(float4*)&g_hbuf[n * 128 + lane * 4] = r;
}

// ---------------- layer 4: 128 -> 12 GEMM (feat5 + fused el5/er5) ----------------
__global__ void __launch_bounds__(384) gemm5_kernel() {
    __shared__ float Ws[128 * 12];
    __shared__ float hs[32 * 128];
    int tid = threadIdx.x;
    int n0 = blockIdx.x * 32;
    for (int i = tid; i < 128 * 12; i += 384) Ws[i] = g_w4ext[i];
    for (int i = tid; i < 4096; i += 384) {
        int gr = n0 + (i >> 7);
        hs[i] = (gr < N_NODES) ? g_hbuf[gr * 128 + (i & 127)] : 0.f;
    }
    __syncthreads();
    int nl = tid / 12, c = tid - nl * 12;
    if (nl >= 32) return;
    int n = n0 + nl;
    if (n >= N_NODES) return;
    float a = 0.f;
#pragma unroll 8
    for (int k = 0; k < 128; k++) a = fmaf(hs[nl * 128 + k], Ws[k * 12 + c], a);
    if (c < 10)      g_feat5[n * 10 + c] = a;
    else if (c == 10) g_el5[n] = a;
    else             g_er5[n] = a;
}

// ---------------- layer 4 aggregation (1 head, 10 dims) -> d_out ----------------
__global__ void __launch_bounds__(256) agg5_kernel(float* __restrict__ out) {
    int warp = (blockIdx.x * blockDim.x + threadIdx.x) >> 5;
    int lane = threadIdx.x & 31;
    if (warp >= N_NODES) return;
    int n = warp;
    int start = g_rowptr[n], end = g_rowptr[n + 1];
    if (start == end) {
        if (lane < 10) out[n * 10 + lane] = 0.f;
        return;
    }
    float ern = g_er5[n];
    float mx = NEG_INF;
    for (int base = start; base < end; base += 32) {
        int j = base + lane;
        float v = NEG_INF;
        if (j < end) {
            int s = g_srcs[j];
            float e = g_el5[s] + ern;
            v = (e >= 0.f) ? e : 0.2f * e;
        }
        mx = fmaxf(mx, v);
    }
#pragma unroll
    for (int off = 16; off >= 1; off >>= 1) mx = fmaxf(mx, __shfl_xor_sync(0xffffffffu, mx, off));

    float dn = 0.f;
    float acc[10];
#pragma unroll
    for (int c = 0; c < 10; c++) acc[c] = 0.f;
    for (int base = start; base < end; base += 32) {
        int j = base + lane;
        if (j < end) {
            int s = g_srcs[j];
            float e = g_el5[s] + ern;
            e = (e >= 0.f) ? e : 0.2f * e;
            float ex = __expf(e - mx);
            dn += ex;
#pragma unroll
            for (int c = 0; c < 10; c++) acc[c] = fmaf(ex, g_feat5[s * 10 + c], acc[c]);
        }
    }
#pragma unroll
    for (int off = 16; off >= 1; off >>= 1) dn += __shfl_xor_sync(0xffffffffu, dn, off);
    float res = 0.f;
#pragma unroll
    for (int c = 0; c < 10; c++) {
        float t = acc[c];
#pragma unroll
        for (int off = 16; off >= 1; off >>= 1) t += __shfl_xor_sync(0xffffffffu, t, off);
        if (lane == c) res = t;
    }
    if (lane < 10) out[n * 10 + lane] = res / dn;
}

// ---------------- launch ----------------
extern "C" void kernel_launch(void* const* d_in, const int* in_sizes, int n_in,
                              void* d_out, int out_size) {
    const float* h   = (const float*)d_in[0];
    const int*   src = (const int*)d_in[1];
    const int*   dst = (const int*)d_in[2];
    const float* W[5]  = {(const float*)d_in[3],  (const float*)d_in[6],  (const float*)d_in[9],
                          (const float*)d_in[12], (const float*)d_in[15]};
    const float* al[5] = {(const float*)d_in[4],  (const float*)d_in[7],  (const float*)d_in[10],
                          (const float*)d_in[13], (const float*)d_in[16]};
    const float* ar[5] = {(const float*)d_in[5],  (const float*)d_in[8],  (const float*)d_in[11],
                          (const float*)d_in[14], (const float*)d_in[17]};
    float* out = (float*)d_out;

    // one-time resources (host-side only; GPU work identical every call)
    static cudaStream_t s2 = nullptr;
    static cudaEvent_t evFork = nullptr, evJoin = nullptr;
    if (s2 == nullptr) {
        cudaStreamCreateWithFlags(&s2, cudaStreamNonBlocking);
        cudaEventCreateWithFlags(&evFork, cudaEventDisableTiming);
        cudaEventCreateWithFlags(&evJoin, cudaEventDisableTiming);
        cudaFuncSetAttribute(gemm128_kernel, cudaFuncAttributeMaxDynamicSharedMemorySize, GEMM_SMEM);
    }

    void* wa_p = nullptr;
    cudaGetSymbolAddress(&wa_p, g_wa);
    const float* wa = (const float*)wa_p;
    void* hbuf_p = nullptr;
    cudaGetSymbolAddress(&hbuf_p, g_hbuf);
    const float* hbuf = (const float*)hbuf_p;

    // fork: CSR build on s2, independent of GEMM0/k_wa on main stream
    cudaEventRecord(evFork, 0);
    cudaStreamWaitEvent(s2, evFork, 0);
    k_zero_rowptr<<<(N_NODES + 1 + 255) / 256, 256, 0, s2>>>();
    k_hist<<<(N_EDGES + 255) / 256, 256, 0, s2>>>(dst);
    k_scan<<<1, 1024, 0, s2>>>();
    k_scatter<<<(N_EDGES + 255) / 256, 256, 0, s2>>>(src, dst);
    cudaEventRecord(evJoin, s2);

    // main stream: weight folding + layer-0 GEMM in parallel with CSR
    k_wa<<<32, 256>>>(W[0], al[0], ar[0], W[1], al[1], ar[1],
                      W[2], al[2], ar[2], W[3], al[3], ar[3]);
    k_wa5<<<1, 128>>>(W[4], al[4], ar[4]);
    gemm128_kernel<<<(N_NODES + 63) / 64, 256, GEMM_SMEM>>>(h, W[0], wa + 0 * 2048);

    // join: aggregation needs the CSR
    cudaStreamWaitEvent(0, evJoin, 0);

    aggregate_kernel<<<(N_NODES * 32 + 255) / 256, 256>>>(1);
    for (int l = 1; l < 4; l++) {
        gemm128_kernel<<<(N_NODES + 63) / 64, 256, GEMM_SMEM>>>(hbuf, W[l], wa + l * 2048);
        aggregate_kernel<<<(N_NODES * 32 + 255) / 256, 256>>>(1);
    }
    gemm5_kernel<<<(N_NODES + 31) / 32, 384>>>();
    agg5_kernel<<<(N_NODES * 32 + 255) / 256, 256>>>(out);
}